// round 1
// baseline (speedup 1.0000x reference)
#include <cuda_runtime.h>
#include <cstddef>

// Problem constants
#define EE   384
#define HH   6
#define HSS  64
#define BB   64
#define TT   256
#define FFD  1536
#define NROWS (BB*TT)          // 16384

// ---------------- scratch (device globals; no allocation allowed) ----------
__device__ float g_q[(size_t)NROWS * EE];
__device__ float g_k[(size_t)NROWS * EE];
__device__ float g_v[(size_t)NROWS * EE];
__device__ float g_att[(size_t)NROWS * EE];
__device__ float g_buf[(size_t)NROWS * EE];
__device__ float g_o1[(size_t)NROWS * EE];
__device__ float g_o2[(size_t)NROWS * EE];
__device__ float g_hidden[(size_t)NROWS * FFD];
__device__ float g_wq[EE * EE];
__device__ float g_wk[EE * EE];
__device__ float g_wv[EE * EE];

// ---------------- weight repack: [H,E,HS] -> row-major [E, E] --------------
__global__ void pack_w_kernel(const float* __restrict__ w, float* __restrict__ o) {
    int idx = blockIdx.x * 256 + threadIdx.x;
    if (idx >= HH * EE * HSS) return;
    int h   = idx / (EE * HSS);
    int rem = idx % (EE * HSS);
    int e   = rem / HSS;
    int s   = rem % HSS;
    o[e * EE + h * HSS + s] = w[idx];
}

// ---------------- generic SGEMM: C[N,M] = A[N,K] @ W[K,M] + bias (opt relu)
__global__ void __launch_bounds__(256)
gemm_kernel(const float* __restrict__ A, const float* __restrict__ W,
            const float* __restrict__ bias, float* __restrict__ C,
            int K, int M, int relu) {
    __shared__ float As[16][65];   // [k][row-in-tile]
    __shared__ float Bs[16][65];   // [k][col-in-tile]
    int col0 = blockIdx.x * 64;
    int row0 = blockIdx.y * 64;
    int tid = threadIdx.x;
    int tx = tid & 15, ty = tid >> 4;
    float acc[4][4] = {};

    for (int kt = 0; kt < K; kt += 16) {
#pragma unroll
        for (int i = 0; i < 4; i++) {
            int lin = tid + i * 256;
            int r = lin >> 4, c = lin & 15;
            As[c][r] = A[(size_t)(row0 + r) * K + kt + c];
            int kr = lin >> 6, cc = lin & 63;
            Bs[kr][cc] = W[(size_t)(kt + kr) * M + col0 + cc];
        }
        __syncthreads();
#pragma unroll
        for (int kk = 0; kk < 16; kk++) {
            float a[4], b[4];
#pragma unroll
            for (int i = 0; i < 4; i++) a[i] = As[kk][ty * 4 + i];
#pragma unroll
            for (int j = 0; j < 4; j++) b[j] = Bs[kk][tx * 4 + j];
#pragma unroll
            for (int i = 0; i < 4; i++)
#pragma unroll
                for (int j = 0; j < 4; j++)
                    acc[i][j] = fmaf(a[i], b[j], acc[i][j]);
        }
        __syncthreads();
    }
#pragma unroll
    for (int i = 0; i < 4; i++) {
#pragma unroll
        for (int j = 0; j < 4; j++) {
            int row = row0 + ty * 4 + i;
            int col = col0 + tx * 4 + j;
            float v = acc[i][j] + bias[col];
            if (relu) v = fmaxf(v, 0.0f);
            C[(size_t)row * M + col] = v;
        }
    }
}

// ---------------- attention: causal, scale = 1/sqrt(E) ---------------------
// One CTA per (b, h, 64-query tile). Q/K/V layout: [B,T,H,HS] == [N, E] with
// head offset h*HS. Smem: sQ[64][65] (s-major), sKV[64][65], sS[64][257].
__global__ void __launch_bounds__(256)
attn_kernel(const float* __restrict__ Q, const float* __restrict__ Kp,
            const float* __restrict__ Vp, float* __restrict__ O) {
    extern __shared__ float sm[];
    float* sQ  = sm;                 // [64][65], [s][ti]
    float* sKV = sm + 64 * 65;       // [64][65]
    float* sS  = sm + 2 * 64 * 65;   // [64][257], [ti][u]

    int bid  = blockIdx.x;
    int tile = bid & 3;
    int h    = (bid >> 2) % HH;
    int b    = bid / (4 * HH);
    int t0   = tile * 64;
    int tid  = threadIdx.x;

    size_t qbase = ((size_t)(b * TT + t0)) * EE + h * HSS;
#pragma unroll
    for (int i = 0; i < 16; i++) {
        int lin = tid + i * 256;
        int ti = lin >> 6, s = lin & 63;
        sQ[s * 65 + ti] = Q[qbase + (size_t)ti * EE + s];
    }

    int tx = tid & 15, ty = tid >> 4;
    const float scale = rsqrtf((float)EE);

    // scores for key tiles 0..tile (causal)
    for (int ut = 0; ut <= tile; ut++) {
        size_t kbase = ((size_t)(b * TT + ut * 64)) * EE + h * HSS;
        __syncthreads();
#pragma unroll
        for (int i = 0; i < 16; i++) {
            int lin = tid + i * 256;
            int ui = lin >> 6, s = lin & 63;
            sKV[s * 65 + ui] = Kp[kbase + (size_t)ui * EE + s];
        }
        __syncthreads();
        float acc[4][4] = {};
#pragma unroll 8
        for (int s = 0; s < 64; s++) {
            float a[4], bb[4];
#pragma unroll
            for (int i = 0; i < 4; i++) a[i] = sQ[s * 65 + ty * 4 + i];
#pragma unroll
            for (int j = 0; j < 4; j++) bb[j] = sKV[s * 65 + tx * 4 + j];
#pragma unroll
            for (int i = 0; i < 4; i++)
#pragma unroll
                for (int j = 0; j < 4; j++)
                    acc[i][j] = fmaf(a[i], bb[j], acc[i][j]);
        }
#pragma unroll
        for (int i = 0; i < 4; i++)
#pragma unroll
            for (int j = 0; j < 4; j++)
                sS[(ty * 4 + i) * 257 + ut * 64 + tx * 4 + j] = acc[i][j] * scale;
    }
    __syncthreads();

    // softmax per query row (rows 0..63 handled by threads 0..63)
    if (tid < 64) {
        int ti = tid;
        int nvalid = t0 + ti + 1;          // causal: keys 0..t inclusive
        int ncomp  = (tile + 1) * 64;      // computed range
        float m = -1e30f;
        for (int u = 0; u < nvalid; u++) m = fmaxf(m, sS[ti * 257 + u]);
        float sum = 0.0f;
        for (int u = 0; u < nvalid; u++) {
            float e = __expf(sS[ti * 257 + u] - m);
            sS[ti * 257 + u] = e;
            sum += e;
        }
        float inv = 1.0f / sum;
        for (int u = 0; u < nvalid; u++) sS[ti * 257 + u] *= inv;
        for (int u = nvalid; u < ncomp; u++) sS[ti * 257 + u] = 0.0f;
    }
    __syncthreads();

    // out = P @ V
    int rowi = tid >> 2;
    int sc0  = (tid & 3) * 16;
    float out[16] = {};
    for (int ut = 0; ut <= tile; ut++) {
        size_t vbase = ((size_t)(b * TT + ut * 64)) * EE + h * HSS;
        __syncthreads();
#pragma unroll
        for (int i = 0; i < 16; i++) {
            int lin = tid + i * 256;
            int ui = lin >> 6, s = lin & 63;
            sKV[ui * 65 + s] = Vp[vbase + (size_t)ui * EE + s];
        }
        __syncthreads();
#pragma unroll 4
        for (int u = 0; u < 64; u++) {
            float p = sS[rowi * 257 + ut * 64 + u];
#pragma unroll
            for (int j = 0; j < 16; j++)
                out[j] = fmaf(p, sKV[u * 65 + sc0 + j], out[j]);
        }
    }
    size_t obase = ((size_t)(b * TT + t0 + rowi)) * EE + h * HSS + sc0;
#pragma unroll
    for (int j = 0; j < 16; j++) O[obase + j] = out[j];
}

// ---------------- fused residual add + LayerNorm ---------------------------
__global__ void __launch_bounds__(128)
add_ln_kernel(const float* __restrict__ a, const float* __restrict__ r,
              const float* __restrict__ g, const float* __restrict__ bt,
              float* __restrict__ o) {
    int row = blockIdx.x;
    int tid = threadIdx.x;
    float v[3];
#pragma unroll
    for (int i = 0; i < 3; i++) {
        int e = tid + i * 128;
        v[i] = a[(size_t)row * EE + e] + r[(size_t)row * EE + e];
    }
    __shared__ float red[4];
    float s = v[0] + v[1] + v[2];
#pragma unroll
    for (int off = 16; off; off >>= 1) s += __shfl_xor_sync(~0u, s, off);
    if ((tid & 31) == 0) red[tid >> 5] = s;
    __syncthreads();
    float mean = (red[0] + red[1] + red[2] + red[3]) * (1.0f / EE);
    __syncthreads();
    float d0 = v[0] - mean, d1 = v[1] - mean, d2 = v[2] - mean;
    float sq = d0 * d0 + d1 * d1 + d2 * d2;
#pragma unroll
    for (int off = 16; off; off >>= 1) sq += __shfl_xor_sync(~0u, sq, off);
    if ((tid & 31) == 0) red[tid >> 5] = sq;
    __syncthreads();
    float var = (red[0] + red[1] + red[2] + red[3]) * (1.0f / EE);
    float inv = rsqrtf(var + 1e-5f);
#pragma unroll
    for (int i = 0; i < 3; i++) {
        int e = tid + i * 128;
        o[(size_t)row * EE + e] = (v[i] - mean) * inv * g[e] + bt[e];
    }
}

// ---------------- host orchestration ---------------------------------------
static const int ATTN_SMEM = (2 * 64 * 65 + 64 * 257) * 4;  // 99072 bytes

extern "C" void kernel_launch(void* const* d_in, const int* in_sizes, int n_in,
                              void* d_out, int out_size) {
    const float* enc = (const float*)d_in[0];
    const float* x   = (const float*)d_in[1];
    const float* sa1_wq = (const float*)d_in[2];
    const float* sa1_bq = (const float*)d_in[3];
    const float* sa1_wk = (const float*)d_in[4];
    const float* sa1_bk = (const float*)d_in[5];
    const float* sa1_wv = (const float*)d_in[6];
    const float* sa1_bv = (const float*)d_in[7];
    const float* sa1_pw = (const float*)d_in[8];
    const float* sa1_pb = (const float*)d_in[9];
    const float* sa2_wq = (const float*)d_in[10];
    const float* sa2_bq = (const float*)d_in[11];
    const float* sa2_wk = (const float*)d_in[12];
    const float* sa2_bk = (const float*)d_in[13];
    const float* sa2_wv = (const float*)d_in[14];
    const float* sa2_bv = (const float*)d_in[15];
    const float* sa2_pw = (const float*)d_in[16];
    const float* sa2_pb = (const float*)d_in[17];
    const float* ff_w1  = (const float*)d_in[18];
    const float* ff_b1  = (const float*)d_in[19];
    const float* ff_w2  = (const float*)d_in[20];
    const float* ff_b2  = (const float*)d_in[21];
    const float* ln1_g  = (const float*)d_in[22];
    const float* ln1_b  = (const float*)d_in[23];
    const float* ln2_g  = (const float*)d_in[24];
    const float* ln2_b  = (const float*)d_in[25];
    const float* ln3_g  = (const float*)d_in[26];
    const float* ln3_b  = (const float*)d_in[27];
    float* out = (float*)d_out;

    cudaFuncSetAttribute(attn_kernel,
                         cudaFuncAttributeMaxDynamicSharedMemorySize, ATTN_SMEM);

    float *pq, *pk, *pv, *patt, *pbuf, *po1, *po2, *phid, *pwq, *pwk, *pwv;
    cudaGetSymbolAddress((void**)&pq,  g_q);
    cudaGetSymbolAddress((void**)&pk,  g_k);
    cudaGetSymbolAddress((void**)&pv,  g_v);
    cudaGetSymbolAddress((void**)&patt, g_att);
    cudaGetSymbolAddress((void**)&pbuf, g_buf);
    cudaGetSymbolAddress((void**)&po1, g_o1);
    cudaGetSymbolAddress((void**)&po2, g_o2);
    cudaGetSymbolAddress((void**)&phid, g_hidden);
    cudaGetSymbolAddress((void**)&pwq, g_wq);
    cudaGetSymbolAddress((void**)&pwk, g_wk);
    cudaGetSymbolAddress((void**)&pwv, g_wv);

    const int PACK_BLOCKS = (HH * EE * HSS + 255) / 256;

    auto gemm = [&](const float* A, const float* W, const float* bias,
                    float* C, int K, int M, int relu) {
        dim3 grid(M / 64, NROWS / 64);
        gemm_kernel<<<grid, 256>>>(A, W, bias, C, K, M, relu);
    };

    // ---- block 1: masked self-attention + add&norm ----
    pack_w_kernel<<<PACK_BLOCKS, 256>>>(sa1_wq, pwq);
    pack_w_kernel<<<PACK_BLOCKS, 256>>>(sa1_wk, pwk);
    pack_w_kernel<<<PACK_BLOCKS, 256>>>(sa1_wv, pwv);
    gemm(x, pwq, sa1_bq, pq, EE, EE, 0);
    gemm(x, pwk, sa1_bk, pk, EE, EE, 0);
    gemm(x, pwv, sa1_bv, pv, EE, EE, 0);
    attn_kernel<<<BB * HH * 4, 256, ATTN_SMEM>>>(pq, pk, pv, patt);
    gemm(patt, sa1_pw, sa1_pb, pbuf, EE, EE, 0);
    add_ln_kernel<<<NROWS, 128>>>(x, pbuf, ln1_g, ln1_b, po1);

    // ---- block 2: cross-attention (still causal-masked) + add&norm ----
    pack_w_kernel<<<PACK_BLOCKS, 256>>>(sa2_wq, pwq);
    pack_w_kernel<<<PACK_BLOCKS, 256>>>(sa2_wk, pwk);
    pack_w_kernel<<<PACK_BLOCKS, 256>>>(sa2_wv, pwv);
    gemm(po1, pwq, sa2_bq, pq, EE, EE, 0);
    gemm(enc, pwk, sa2_bk, pk, EE, EE, 0);
    gemm(enc, pwv, sa2_bv, pv, EE, EE, 0);
    attn_kernel<<<BB * HH * 4, 256, ATTN_SMEM>>>(pq, pk, pv, patt);
    gemm(patt, sa2_pw, sa2_pb, pbuf, EE, EE, 0);
    add_ln_kernel<<<NROWS, 128>>>(po1, pbuf, ln2_g, ln2_b, po2);

    // ---- FFN + add&norm ----
    gemm(po2, ff_w1, ff_b1, phid, EE, FFD, 1);
    gemm(phid, ff_w2, ff_b2, pbuf, FFD, EE, 0);
    add_ln_kernel<<<NROWS, 128>>>(po2, pbuf, ln3_g, ln3_b, out);
}

// round 2
// speedup vs baseline: 2.1499x; 2.1499x over previous
#include <cuda_runtime.h>
#include <cstdint>
#include <cstddef>

// Problem constants
#define EE   384
#define HH   6
#define HSS  64
#define BB   64
#define TT   256
#define FFD  1536
#define NROWS (BB*TT)          // 16384

// ---------------- scratch (device globals; no allocation allowed) ----------
__device__ float g_q[(size_t)NROWS * EE];
__device__ float g_k[(size_t)NROWS * EE];
__device__ float g_v[(size_t)NROWS * EE];
__device__ float g_att[(size_t)NROWS * EE];
__device__ float g_buf[(size_t)NROWS * EE];
__device__ float g_o1[(size_t)NROWS * EE];
__device__ float g_o2[(size_t)NROWS * EE];
__device__ float g_hidden[(size_t)NROWS * FFD];
__device__ float g_wq[EE * EE];
__device__ float g_wk[EE * EE];
__device__ float g_wv[EE * EE];

// ---------------- weight repack: [H,E,HS] -> row-major [E, E] --------------
__global__ void pack_w_kernel(const float* __restrict__ w, float* __restrict__ o) {
    int idx = blockIdx.x * 256 + threadIdx.x;
    if (idx >= HH * EE * HSS) return;
    int h   = idx / (EE * HSS);
    int rem = idx % (EE * HSS);
    int e   = rem / HSS;
    int s   = rem % HSS;
    o[e * EE + h * HSS + s] = w[idx];
}

// ---------------- TF32 tensor-core GEMM -----------------------------------
// C[N,M] = A[N,K] @ W[K,M] + bias, optional relu.
// 128x128 CTA tile, BK=32, 8 warps each computing 64x32, mma.m16n8k8 tf32.
#define AS_STRIDE 36          // 32 + 4 pad  (fragment A reads conflict-free)
#define BS_STRIDE 136         // 128 + 8 pad (fragment B reads conflict-free)
#define BUF_FLOATS (128*AS_STRIDE + 32*BS_STRIDE)   // 8960 floats per buffer
#define GEMM_SMEM (2 * BUF_FLOATS * 4)              // 71680 bytes

__device__ __forceinline__ uint32_t f2tf(float f) {
    uint32_t u;
    asm("cvt.rna.tf32.f32 %0, %1;" : "=r"(u) : "f"(f));
    return u;
}
__device__ __forceinline__ void mma_tf32(float* c, const uint32_t* a, const uint32_t* b) {
    asm volatile(
        "mma.sync.aligned.m16n8k8.row.col.f32.tf32.tf32.f32 "
        "{%0,%1,%2,%3}, {%4,%5,%6,%7}, {%8,%9}, {%0,%1,%2,%3};"
        : "+f"(c[0]), "+f"(c[1]), "+f"(c[2]), "+f"(c[3])
        : "r"(a[0]), "r"(a[1]), "r"(a[2]), "r"(a[3]), "r"(b[0]), "r"(b[1]));
}
__device__ __forceinline__ void cp16(uint32_t dst, const void* src) {
    asm volatile("cp.async.cg.shared.global [%0], [%1], 16;" :: "r"(dst), "l"(src));
}

__device__ __forceinline__ void load_tiles(uint32_t as_base, uint32_t bs_base,
                                           const float* __restrict__ A,
                                           const float* __restrict__ W,
                                           int row0, int col0, int kt,
                                           int K, int M, int tid) {
#pragma unroll
    for (int i = 0; i < 4; i++) {        // A: 128 rows x 32 k -> 1024 float4
        int li = tid + i * 256;
        int r = li >> 3, c4 = li & 7;
        cp16(as_base + (uint32_t)(r * AS_STRIDE + c4 * 4) * 4,
             A + (size_t)(row0 + r) * K + kt + c4 * 4);
    }
#pragma unroll
    for (int i = 0; i < 4; i++) {        // W: 32 k x 128 cols -> 1024 float4
        int li = tid + i * 256;
        int kr = li >> 5, c4 = li & 31;
        cp16(bs_base + (uint32_t)(kr * BS_STRIDE + c4 * 4) * 4,
             W + (size_t)(kt + kr) * M + col0 + c4 * 4);
    }
}

__global__ void __launch_bounds__(256)
gemm_tc_kernel(const float* __restrict__ A, const float* __restrict__ W,
               const float* __restrict__ bias, float* __restrict__ C,
               int K, int M, int relu) {
    extern __shared__ float sm[];
    float* As[2] = { sm, sm + BUF_FLOATS };
    float* Bs[2] = { sm + 128 * AS_STRIDE, sm + BUF_FLOATS + 128 * AS_STRIDE };
    uint32_t as_u[2], bs_u[2];
#pragma unroll
    for (int s = 0; s < 2; s++) {
        as_u[s] = (uint32_t)__cvta_generic_to_shared(As[s]);
        bs_u[s] = (uint32_t)__cvta_generic_to_shared(Bs[s]);
    }

    int col0 = blockIdx.x * 128;
    int row0 = blockIdx.y * 128;
    int tid  = threadIdx.x;
    int lane = tid & 31, warp = tid >> 5;
    int wm = warp >> 2, wn = warp & 3;       // 2 x 4 warp grid
    int gid = lane >> 2, tg = lane & 3;

    float acc[4][4][4];
#pragma unroll
    for (int i = 0; i < 4; i++)
#pragma unroll
        for (int j = 0; j < 4; j++)
#pragma unroll
            for (int r = 0; r < 4; r++) acc[i][j][r] = 0.0f;

    load_tiles(as_u[0], bs_u[0], A, W, row0, col0, 0, K, M, tid);
    asm volatile("cp.async.commit_group;");

    int buf = 0;
    for (int kt = 0; kt < K; kt += 32, buf ^= 1) {
        if (kt + 32 < K) {
            load_tiles(as_u[buf ^ 1], bs_u[buf ^ 1], A, W, row0, col0, kt + 32, K, M, tid);
            asm volatile("cp.async.commit_group;");
            asm volatile("cp.async.wait_group 1;");
        } else {
            asm volatile("cp.async.wait_group 0;");
        }
        __syncthreads();

        const float* as = As[buf];
        const float* bs = Bs[buf];
#pragma unroll
        for (int ks = 0; ks < 4; ks++) {
            int k0 = ks * 8;
            uint32_t af[4][4], bf[4][2];
#pragma unroll
            for (int mt = 0; mt < 4; mt++) {
                int ar = wm * 64 + mt * 16 + gid;
                af[mt][0] = f2tf(as[ar * AS_STRIDE + k0 + tg]);
                af[mt][1] = f2tf(as[(ar + 8) * AS_STRIDE + k0 + tg]);
                af[mt][2] = f2tf(as[ar * AS_STRIDE + k0 + tg + 4]);
                af[mt][3] = f2tf(as[(ar + 8) * AS_STRIDE + k0 + tg + 4]);
            }
#pragma unroll
            for (int nt = 0; nt < 4; nt++) {
                int bc = wn * 32 + nt * 8 + gid;
                bf[nt][0] = f2tf(bs[(k0 + tg) * BS_STRIDE + bc]);
                bf[nt][1] = f2tf(bs[(k0 + tg + 4) * BS_STRIDE + bc]);
            }
#pragma unroll
            for (int mt = 0; mt < 4; mt++)
#pragma unroll
                for (int nt = 0; nt < 4; nt++)
                    mma_tf32(acc[mt][nt], af[mt], bf[nt]);
        }
        __syncthreads();
    }

    // epilogue: bias (+relu), direct global stores
#pragma unroll
    for (int mt = 0; mt < 4; mt++) {
#pragma unroll
        for (int nt = 0; nt < 4; nt++) {
            int r0 = row0 + wm * 64 + mt * 16 + gid;
            int c0 = col0 + wn * 32 + nt * 8 + tg * 2;
            float b0 = bias[c0], b1 = bias[c0 + 1];
            float v0 = acc[mt][nt][0] + b0;
            float v1 = acc[mt][nt][1] + b1;
            float v2 = acc[mt][nt][2] + b0;
            float v3 = acc[mt][nt][3] + b1;
            if (relu) {
                v0 = fmaxf(v0, 0.0f); v1 = fmaxf(v1, 0.0f);
                v2 = fmaxf(v2, 0.0f); v3 = fmaxf(v3, 0.0f);
            }
            C[(size_t)r0 * M + c0]           = v0;
            C[(size_t)r0 * M + c0 + 1]       = v1;
            C[(size_t)(r0 + 8) * M + c0]     = v2;
            C[(size_t)(r0 + 8) * M + c0 + 1] = v3;
        }
    }
}

// ---------------- attention: causal, scale = 1/sqrt(E) ---------------------
__global__ void __launch_bounds__(256)
attn_kernel(const float* __restrict__ Q, const float* __restrict__ Kp,
            const float* __restrict__ Vp, float* __restrict__ O) {
    extern __shared__ float smn[];
    float* sQ  = smn;                 // [64][65], [s][ti]
    float* sKV = smn + 64 * 65;       // [64][65]
    float* sS  = smn + 2 * 64 * 65;   // [64][257], [ti][u]

    int bid  = blockIdx.x;
    int tile = bid & 3;
    int h    = (bid >> 2) % HH;
    int b    = bid / (4 * HH);
    int t0   = tile * 64;
    int tid  = threadIdx.x;

    size_t qbase = ((size_t)(b * TT + t0)) * EE + h * HSS;
#pragma unroll
    for (int i = 0; i < 16; i++) {
        int lin = tid + i * 256;
        int ti = lin >> 6, s = lin & 63;
        sQ[s * 65 + ti] = Q[qbase + (size_t)ti * EE + s];
    }

    int tx = tid & 15, ty = tid >> 4;
    const float scale = rsqrtf((float)EE);

    for (int ut = 0; ut <= tile; ut++) {
        size_t kbase = ((size_t)(b * TT + ut * 64)) * EE + h * HSS;
        __syncthreads();
#pragma unroll
        for (int i = 0; i < 16; i++) {
            int lin = tid + i * 256;
            int ui = lin >> 6, s = lin & 63;
            sKV[s * 65 + ui] = Kp[kbase + (size_t)ui * EE + s];
        }
        __syncthreads();
        float acc[4][4] = {};
#pragma unroll 8
        for (int s = 0; s < 64; s++) {
            float a[4], bb[4];
#pragma unroll
            for (int i = 0; i < 4; i++) a[i] = sQ[s * 65 + ty * 4 + i];
#pragma unroll
            for (int j = 0; j < 4; j++) bb[j] = sKV[s * 65 + tx * 4 + j];
#pragma unroll
            for (int i = 0; i < 4; i++)
#pragma unroll
                for (int j = 0; j < 4; j++)
                    acc[i][j] = fmaf(a[i], bb[j], acc[i][j]);
        }
#pragma unroll
        for (int i = 0; i < 4; i++)
#pragma unroll
            for (int j = 0; j < 4; j++)
                sS[(ty * 4 + i) * 257 + ut * 64 + tx * 4 + j] = acc[i][j] * scale;
    }
    __syncthreads();

    if (tid < 64) {
        int ti = tid;
        int nvalid = t0 + ti + 1;
        int ncomp  = (tile + 1) * 64;
        float m = -1e30f;
        for (int u = 0; u < nvalid; u++) m = fmaxf(m, sS[ti * 257 + u]);
        float sum = 0.0f;
        for (int u = 0; u < nvalid; u++) {
            float e = __expf(sS[ti * 257 + u] - m);
            sS[ti * 257 + u] = e;
            sum += e;
        }
        float inv = 1.0f / sum;
        for (int u = 0; u < nvalid; u++) sS[ti * 257 + u] *= inv;
        for (int u = nvalid; u < ncomp; u++) sS[ti * 257 + u] = 0.0f;
    }
    __syncthreads();

    int rowi = tid >> 2;
    int sc0  = (tid & 3) * 16;
    float out[16] = {};
    for (int ut = 0; ut <= tile; ut++) {
        size_t vbase = ((size_t)(b * TT + ut * 64)) * EE + h * HSS;
        __syncthreads();
#pragma unroll
        for (int i = 0; i < 16; i++) {
            int lin = tid + i * 256;
            int ui = lin >> 6, s = lin & 63;
            sKV[ui * 65 + s] = Vp[vbase + (size_t)ui * EE + s];
        }
        __syncthreads();
#pragma unroll 4
        for (int u = 0; u < 64; u++) {
            float p = sS[rowi * 257 + ut * 64 + u];
#pragma unroll
            for (int j = 0; j < 16; j++)
                out[j] = fmaf(p, sKV[u * 65 + sc0 + j], out[j]);
        }
    }
    size_t obase = ((size_t)(b * TT + t0 + rowi)) * EE + h * HSS + sc0;
#pragma unroll
    for (int j = 0; j < 16; j++) O[obase + j] = out[j];
}

// ---------------- fused residual add + LayerNorm ---------------------------
__global__ void __launch_bounds__(128)
add_ln_kernel(const float* __restrict__ a, const float* __restrict__ r,
              const float* __restrict__ g, const float* __restrict__ bt,
              float* __restrict__ o) {
    int row = blockIdx.x;
    int tid = threadIdx.x;
    float v[3];
#pragma unroll
    for (int i = 0; i < 3; i++) {
        int e = tid + i * 128;
        v[i] = a[(size_t)row * EE + e] + r[(size_t)row * EE + e];
    }
    __shared__ float red[4];
    float s = v[0] + v[1] + v[2];
#pragma unroll
    for (int off = 16; off; off >>= 1) s += __shfl_xor_sync(~0u, s, off);
    if ((tid & 31) == 0) red[tid >> 5] = s;
    __syncthreads();
    float mean = (red[0] + red[1] + red[2] + red[3]) * (1.0f / EE);
    __syncthreads();
    float d0 = v[0] - mean, d1 = v[1] - mean, d2 = v[2] - mean;
    float sq = d0 * d0 + d1 * d1 + d2 * d2;
#pragma unroll
    for (int off = 16; off; off >>= 1) sq += __shfl_xor_sync(~0u, sq, off);
    if ((tid & 31) == 0) red[tid >> 5] = sq;
    __syncthreads();
    float var = (red[0] + red[1] + red[2] + red[3]) * (1.0f / EE);
    float inv = rsqrtf(var + 1e-5f);
#pragma unroll
    for (int i = 0; i < 3; i++) {
        int e = tid + i * 128;
        o[(size_t)row * EE + e] = (v[i] - mean) * inv * g[e] + bt[e];
    }
}

// ---------------- host orchestration ---------------------------------------
static const int ATTN_SMEM = (2 * 64 * 65 + 64 * 257) * 4;  // 99072 bytes

extern "C" void kernel_launch(void* const* d_in, const int* in_sizes, int n_in,
                              void* d_out, int out_size) {
    const float* enc = (const float*)d_in[0];
    const float* x   = (const float*)d_in[1];
    const float* sa1_wq = (const float*)d_in[2];
    const float* sa1_bq = (const float*)d_in[3];
    const float* sa1_wk = (const float*)d_in[4];
    const float* sa1_bk = (const float*)d_in[5];
    const float* sa1_wv = (const float*)d_in[6];
    const float* sa1_bv = (const float*)d_in[7];
    const float* sa1_pw = (const float*)d_in[8];
    const float* sa1_pb = (const float*)d_in[9];
    const float* sa2_wq = (const float*)d_in[10];
    const float* sa2_bq = (const float*)d_in[11];
    const float* sa2_wk = (const float*)d_in[12];
    const float* sa2_bk = (const float*)d_in[13];
    const float* sa2_wv = (const float*)d_in[14];
    const float* sa2_bv = (const float*)d_in[15];
    const float* sa2_pw = (const float*)d_in[16];
    const float* sa2_pb = (const float*)d_in[17];
    const float* ff_w1  = (const float*)d_in[18];
    const float* ff_b1  = (const float*)d_in[19];
    const float* ff_w2  = (const float*)d_in[20];
    const float* ff_b2  = (const float*)d_in[21];
    const float* ln1_g  = (const float*)d_in[22];
    const float* ln1_b  = (const float*)d_in[23];
    const float* ln2_g  = (const float*)d_in[24];
    const float* ln2_b  = (const float*)d_in[25];
    const float* ln3_g  = (const float*)d_in[26];
    const float* ln3_b  = (const float*)d_in[27];
    float* out = (float*)d_out;

    cudaFuncSetAttribute(attn_kernel,
                         cudaFuncAttributeMaxDynamicSharedMemorySize, ATTN_SMEM);
    cudaFuncSetAttribute(gemm_tc_kernel,
                         cudaFuncAttributeMaxDynamicSharedMemorySize, GEMM_SMEM);

    float *pq, *pk, *pv, *patt, *pbuf, *po1, *po2, *phid, *pwq, *pwk, *pwv;
    cudaGetSymbolAddress((void**)&pq,  g_q);
    cudaGetSymbolAddress((void**)&pk,  g_k);
    cudaGetSymbolAddress((void**)&pv,  g_v);
    cudaGetSymbolAddress((void**)&patt, g_att);
    cudaGetSymbolAddress((void**)&pbuf, g_buf);
    cudaGetSymbolAddress((void**)&po1, g_o1);
    cudaGetSymbolAddress((void**)&po2, g_o2);
    cudaGetSymbolAddress((void**)&phid, g_hidden);
    cudaGetSymbolAddress((void**)&pwq, g_wq);
    cudaGetSymbolAddress((void**)&pwk, g_wk);
    cudaGetSymbolAddress((void**)&pwv, g_wv);

    const int PACK_BLOCKS = (HH * EE * HSS + 255) / 256;

    auto gemm = [&](const float* A, const float* W, const float* bias,
                    float* C, int K, int M, int relu) {
        dim3 grid(M / 128, NROWS / 128);
        gemm_tc_kernel<<<grid, 256, GEMM_SMEM>>>(A, W, bias, C, K, M, relu);
    };

    // ---- block 1: masked self-attention + add&norm ----
    pack_w_kernel<<<PACK_BLOCKS, 256>>>(sa1_wq, pwq);
    pack_w_kernel<<<PACK_BLOCKS, 256>>>(sa1_wk, pwk);
    pack_w_kernel<<<PACK_BLOCKS, 256>>>(sa1_wv, pwv);
    gemm(x, pwq, sa1_bq, pq, EE, EE, 0);
    gemm(x, pwk, sa1_bk, pk, EE, EE, 0);
    gemm(x, pwv, sa1_bv, pv, EE, EE, 0);
    attn_kernel<<<BB * HH * 4, 256, ATTN_SMEM>>>(pq, pk, pv, patt);
    gemm(patt, sa1_pw, sa1_pb, pbuf, EE, EE, 0);
    add_ln_kernel<<<NROWS, 128>>>(x, pbuf, ln1_g, ln1_b, po1);

    // ---- block 2: cross-attention (still causal-masked) + add&norm ----
    pack_w_kernel<<<PACK_BLOCKS, 256>>>(sa2_wq, pwq);
    pack_w_kernel<<<PACK_BLOCKS, 256>>>(sa2_wk, pwk);
    pack_w_kernel<<<PACK_BLOCKS, 256>>>(sa2_wv, pwv);
    gemm(po1, pwq, sa2_bq, pq, EE, EE, 0);
    gemm(enc, pwk, sa2_bk, pk, EE, EE, 0);
    gemm(enc, pwv, sa2_bv, pv, EE, EE, 0);
    attn_kernel<<<BB * HH * 4, 256, ATTN_SMEM>>>(pq, pk, pv, patt);
    gemm(patt, sa2_pw, sa2_pb, pbuf, EE, EE, 0);
    add_ln_kernel<<<NROWS, 128>>>(po1, pbuf, ln2_g, ln2_b, po2);

    // ---- FFN + add&norm ----
    gemm(po2, ff_w1, ff_b1, phid, EE, FFD, 1);
    gemm(phid, ff_w2, ff_b2, pbuf, FFD, EE, 0);
    add_ln_kernel<<<NROWS, 128>>>(po2, pbuf, ln3_g, ln3_b, out);
}

// round 3
// speedup vs baseline: 3.5978x; 1.6735x over previous
#include <cuda_runtime.h>
#include <cstdint>
#include <cstddef>

// Problem constants
#define EE   384
#define HH   6
#define HSS  64
#define BB   64
#define TT   256
#define FFD  1536
#define NROWS (BB*TT)          // 16384

// ---------------- scratch (device globals; no allocation allowed) ----------
__device__ float g_qkv[(size_t)NROWS * 3 * EE];   // fused Q|K|V, stride 1152
__device__ float g_kv[(size_t)NROWS * 2 * EE];    // fused K|V (cross), stride 768
__device__ float g_q[(size_t)NROWS * EE];
__device__ float g_att[(size_t)NROWS * EE];
__device__ float g_buf[(size_t)NROWS * EE];
__device__ float g_o1[(size_t)NROWS * EE];
__device__ float g_o2[(size_t)NROWS * EE];
__device__ float g_hidden[(size_t)NROWS * FFD];
__device__ float g_wqkv[EE * 3 * EE];
__device__ float g_wkv[EE * 2 * EE];
__device__ float g_wq[EE * EE];
__device__ float g_bqkv[3 * EE];
__device__ float g_bkv[2 * EE];

// ---------------- weight repack: [H,E,HS] -> row-major [E, ldo] at col0 ----
__global__ void pack_w_kernel(const float* __restrict__ w, float* __restrict__ o,
                              int ldo, int col0) {
    int idx = blockIdx.x * 256 + threadIdx.x;
    if (idx >= HH * EE * HSS) return;
    int h   = idx / (EE * HSS);
    int rem = idx % (EE * HSS);
    int e   = rem / HSS;
    int s   = rem % HSS;
    o[(size_t)e * ldo + col0 + h * HSS + s] = w[idx];
}

// concat up to 3 bias vectors of length n
__global__ void pack_bias_kernel(const float* __restrict__ a,
                                 const float* __restrict__ b,
                                 const float* __restrict__ c,
                                 float* __restrict__ o, int n, int cnt) {
    int i = blockIdx.x * 256 + threadIdx.x;
    if (i >= n * cnt) return;
    if (i < n) o[i] = a[i];
    else if (i < 2 * n) o[i] = b[i - n];
    else o[i] = c[i - 2 * n];
}

// ---------------- TF32 tensor-core GEMM -----------------------------------
#define AS_STRIDE 36
#define BS_STRIDE 136
#define BUF_FLOATS (128*AS_STRIDE + 32*BS_STRIDE)
#define GEMM_SMEM (2 * BUF_FLOATS * 4)

__device__ __forceinline__ uint32_t f2tf(float f) {
    uint32_t u;
    asm("cvt.rna.tf32.f32 %0, %1;" : "=r"(u) : "f"(f));
    return u;
}
__device__ __forceinline__ void mma_tf32(float* c, const uint32_t* a, const uint32_t* b) {
    asm volatile(
        "mma.sync.aligned.m16n8k8.row.col.f32.tf32.tf32.f32 "
        "{%0,%1,%2,%3}, {%4,%5,%6,%7}, {%8,%9}, {%0,%1,%2,%3};"
        : "+f"(c[0]), "+f"(c[1]), "+f"(c[2]), "+f"(c[3])
        : "r"(a[0]), "r"(a[1]), "r"(a[2]), "r"(a[3]), "r"(b[0]), "r"(b[1]));
}
__device__ __forceinline__ void cp16(uint32_t dst, const void* src) {
    asm volatile("cp.async.cg.shared.global [%0], [%1], 16;" :: "r"(dst), "l"(src));
}

__device__ __forceinline__ void load_tiles(uint32_t as_base, uint32_t bs_base,
                                           const float* __restrict__ A,
                                           const float* __restrict__ W,
                                           int row0, int col0, int kt,
                                           int K, int M, int tid) {
#pragma unroll
    for (int i = 0; i < 4; i++) {
        int li = tid + i * 256;
        int r = li >> 3, c4 = li & 7;
        cp16(as_base + (uint32_t)(r * AS_STRIDE + c4 * 4) * 4,
             A + (size_t)(row0 + r) * K + kt + c4 * 4);
    }
#pragma unroll
    for (int i = 0; i < 4; i++) {
        int li = tid + i * 256;
        int kr = li >> 5, c4 = li & 31;
        cp16(bs_base + (uint32_t)(kr * BS_STRIDE + c4 * 4) * 4,
             W + (size_t)(kt + kr) * M + col0 + c4 * 4);
    }
}

__global__ void __launch_bounds__(256, 2)
gemm_tc_kernel(const float* __restrict__ A, const float* __restrict__ W,
               const float* __restrict__ bias, float* __restrict__ C,
               int K, int M, int relu) {
    extern __shared__ float sm[];
    float* As[2] = { sm, sm + BUF_FLOATS };
    float* Bs[2] = { sm + 128 * AS_STRIDE, sm + BUF_FLOATS + 128 * AS_STRIDE };
    uint32_t as_u[2], bs_u[2];
#pragma unroll
    for (int s = 0; s < 2; s++) {
        as_u[s] = (uint32_t)__cvta_generic_to_shared(As[s]);
        bs_u[s] = (uint32_t)__cvta_generic_to_shared(Bs[s]);
    }

    int col0 = blockIdx.x * 128;
    int row0 = blockIdx.y * 128;
    int tid  = threadIdx.x;
    int lane = tid & 31, warp = tid >> 5;
    int wm = warp >> 2, wn = warp & 3;
    int gid = lane >> 2, tg = lane & 3;

    float acc[4][4][4];
#pragma unroll
    for (int i = 0; i < 4; i++)
#pragma unroll
        for (int j = 0; j < 4; j++)
#pragma unroll
            for (int r = 0; r < 4; r++) acc[i][j][r] = 0.0f;

    load_tiles(as_u[0], bs_u[0], A, W, row0, col0, 0, K, M, tid);
    asm volatile("cp.async.commit_group;");

    int buf = 0;
    for (int kt = 0; kt < K; kt += 32, buf ^= 1) {
        if (kt + 32 < K) {
            load_tiles(as_u[buf ^ 1], bs_u[buf ^ 1], A, W, row0, col0, kt + 32, K, M, tid);
            asm volatile("cp.async.commit_group;");
            asm volatile("cp.async.wait_group 1;");
        } else {
            asm volatile("cp.async.wait_group 0;");
        }
        __syncthreads();

        const float* as = As[buf];
        const float* bs = Bs[buf];
#pragma unroll
        for (int ks = 0; ks < 4; ks++) {
            int k0 = ks * 8;
            uint32_t af[4][4], bf[4][2];
#pragma unroll
            for (int mt = 0; mt < 4; mt++) {
                int ar = wm * 64 + mt * 16 + gid;
                af[mt][0] = f2tf(as[ar * AS_STRIDE + k0 + tg]);
                af[mt][1] = f2tf(as[(ar + 8) * AS_STRIDE + k0 + tg]);
                af[mt][2] = f2tf(as[ar * AS_STRIDE + k0 + tg + 4]);
                af[mt][3] = f2tf(as[(ar + 8) * AS_STRIDE + k0 + tg + 4]);
            }
#pragma unroll
            for (int nt = 0; nt < 4; nt++) {
                int bc = wn * 32 + nt * 8 + gid;
                bf[nt][0] = f2tf(bs[(k0 + tg) * BS_STRIDE + bc]);
                bf[nt][1] = f2tf(bs[(k0 + tg + 4) * BS_STRIDE + bc]);
            }
#pragma unroll
            for (int mt = 0; mt < 4; mt++)
#pragma unroll
                for (int nt = 0; nt < 4; nt++)
                    mma_tf32(acc[mt][nt], af[mt], bf[nt]);
        }
        __syncthreads();
    }

#pragma unroll
    for (int mt = 0; mt < 4; mt++) {
#pragma unroll
        for (int nt = 0; nt < 4; nt++) {
            int r0 = row0 + wm * 64 + mt * 16 + gid;
            int c0 = col0 + wn * 32 + nt * 8 + tg * 2;
            float b0 = bias[c0], b1 = bias[c0 + 1];
            float v0 = acc[mt][nt][0] + b0;
            float v1 = acc[mt][nt][1] + b1;
            float v2 = acc[mt][nt][2] + b0;
            float v3 = acc[mt][nt][3] + b1;
            if (relu) {
                v0 = fmaxf(v0, 0.0f); v1 = fmaxf(v1, 0.0f);
                v2 = fmaxf(v2, 0.0f); v3 = fmaxf(v3, 0.0f);
            }
            C[(size_t)r0 * M + c0]           = v0;
            C[(size_t)r0 * M + c0 + 1]       = v1;
            C[(size_t)(r0 + 8) * M + c0]     = v2;
            C[(size_t)(r0 + 8) * M + c0 + 1] = v3;
        }
    }
}

// ---------------- tensor-core attention ------------------------------------
// One CTA per (b, h, 64-query tile). 8 warps in 4x2 layout; warp tile 16x32.
// smem strides 68 / 260 give conflict-free mma fragment loads.
#define SQ_STR  68
#define SS_STR  260
#define ATTN_SMEM ((2*64*SQ_STR + 64*SS_STR) * 4)   // 101376 bytes

__global__ void __launch_bounds__(256)
attn_tc_kernel(const float* __restrict__ Q, int ldq,
               const float* __restrict__ Kp, const float* __restrict__ Vp, int ldkv,
               float* __restrict__ O) {
    extern __shared__ float smn[];
    float* sQ  = smn;                  // [64][68] row-major [ti][s]
    float* sKV = smn + 64 * SQ_STR;    // [64][68]
    float* sS  = smn + 2 * 64 * SQ_STR;// [64][260] [ti][u]

    int bid  = blockIdx.x;
    int tile = bid & 3;
    int h    = (bid >> 2) % HH;
    int b    = bid / (4 * HH);
    int t0   = tile * 64;
    int tid  = threadIdx.x;
    int lane = tid & 31, warp = tid >> 5;
    int wm = warp >> 1, wn = warp & 1;    // 4 x 2 warps
    int gid = lane >> 2, tg = lane & 3;
    int am = wm * 16;

    size_t qbase = (size_t)(b * TT + t0) * ldq + h * HSS;
#pragma unroll
    for (int i = 0; i < 16; i++) {
        int lin = tid + i * 256;
        int ti = lin >> 6, s = lin & 63;
        sQ[ti * SQ_STR + s] = Q[qbase + (size_t)ti * ldq + s];
    }

    const float scale = rsqrtf((float)EE);

    // phase 1: S = Q K^T for key tiles 0..tile
    for (int ut = 0; ut <= tile; ut++) {
        size_t kbase = (size_t)(b * TT + ut * 64) * ldkv + h * HSS;
        __syncthreads();
#pragma unroll
        for (int i = 0; i < 16; i++) {
            int lin = tid + i * 256;
            int ui = lin >> 6, s = lin & 63;
            sKV[ui * SQ_STR + s] = Kp[kbase + (size_t)ui * ldkv + s];
        }
        __syncthreads();
        float acc[4][4] = {};
#pragma unroll
        for (int ks = 0; ks < 8; ks++) {
            int k0 = ks * 8;
            uint32_t af[4];
            af[0] = f2tf(sQ[(am + gid) * SQ_STR + k0 + tg]);
            af[1] = f2tf(sQ[(am + gid + 8) * SQ_STR + k0 + tg]);
            af[2] = f2tf(sQ[(am + gid) * SQ_STR + k0 + tg + 4]);
            af[3] = f2tf(sQ[(am + gid + 8) * SQ_STR + k0 + tg + 4]);
#pragma unroll
            for (int nt = 0; nt < 4; nt++) {
                int n = wn * 32 + nt * 8 + gid;
                uint32_t bf[2];
                bf[0] = f2tf(sKV[n * SQ_STR + k0 + tg]);
                bf[1] = f2tf(sKV[n * SQ_STR + k0 + tg + 4]);
                mma_tf32(acc[nt], af, bf);
            }
        }
#pragma unroll
        for (int nt = 0; nt < 4; nt++) {
            int c0 = ut * 64 + wn * 32 + nt * 8 + tg * 2;
            sS[(am + gid) * SS_STR + c0]         = acc[nt][0] * scale;
            sS[(am + gid) * SS_STR + c0 + 1]     = acc[nt][1] * scale;
            sS[(am + gid + 8) * SS_STR + c0]     = acc[nt][2] * scale;
            sS[(am + gid + 8) * SS_STR + c0 + 1] = acc[nt][3] * scale;
        }
    }
    __syncthreads();

    // phase 2: softmax, 4 threads per query row
    {
        int row = tid >> 2, tg4 = tid & 3;
        int nvalid = t0 + row + 1;
        int ncomp  = (tile + 1) * 64;
        float m = -1e30f;
        for (int u = tg4; u < nvalid; u += 4)
            m = fmaxf(m, sS[row * SS_STR + u]);
        m = fmaxf(m, __shfl_xor_sync(~0u, m, 1));
        m = fmaxf(m, __shfl_xor_sync(~0u, m, 2));
        float sum = 0.0f;
        for (int u = tg4; u < ncomp; u += 4) {
            float e = (u < nvalid) ? __expf(sS[row * SS_STR + u] - m) : 0.0f;
            sS[row * SS_STR + u] = e;
            sum += e;
        }
        sum += __shfl_xor_sync(~0u, sum, 1);
        sum += __shfl_xor_sync(~0u, sum, 2);
        float inv = 1.0f / sum;
        for (int u = tg4; u < ncomp; u += 4)
            sS[row * SS_STR + u] *= inv;
    }

    // phase 3: O = P V
    float acc2[4][4] = {};
    for (int ut = 0; ut <= tile; ut++) {
        size_t vbase = (size_t)(b * TT + ut * 64) * ldkv + h * HSS;
        __syncthreads();
#pragma unroll
        for (int i = 0; i < 16; i++) {
            int lin = tid + i * 256;
            int ui = lin >> 6, s = lin & 63;
            sKV[s * SQ_STR + ui] = Vp[vbase + (size_t)ui * ldkv + s];  // [s][u]
        }
        __syncthreads();
#pragma unroll
        for (int ks = 0; ks < 8; ks++) {
            int k0 = ks * 8;
            uint32_t af[4];
            af[0] = f2tf(sS[(am + gid) * SS_STR + ut * 64 + k0 + tg]);
            af[1] = f2tf(sS[(am + gid + 8) * SS_STR + ut * 64 + k0 + tg]);
            af[2] = f2tf(sS[(am + gid) * SS_STR + ut * 64 + k0 + tg + 4]);
            af[3] = f2tf(sS[(am + gid + 8) * SS_STR + ut * 64 + k0 + tg + 4]);
#pragma unroll
            for (int nt = 0; nt < 4; nt++) {
                int n = wn * 32 + nt * 8 + gid;
                uint32_t bf[2];
                bf[0] = f2tf(sKV[n * SQ_STR + k0 + tg]);
                bf[1] = f2tf(sKV[n * SQ_STR + k0 + tg + 4]);
                mma_tf32(acc2[nt], af, bf);
            }
        }
    }
    size_t obase = (size_t)(b * TT + t0) * EE + h * HSS;
#pragma unroll
    for (int nt = 0; nt < 4; nt++) {
        int c0 = wn * 32 + nt * 8 + tg * 2;
        O[obase + (size_t)(am + gid) * EE + c0]         = acc2[nt][0];
        O[obase + (size_t)(am + gid) * EE + c0 + 1]     = acc2[nt][1];
        O[obase + (size_t)(am + gid + 8) * EE + c0]     = acc2[nt][2];
        O[obase + (size_t)(am + gid + 8) * EE + c0 + 1] = acc2[nt][3];
    }
}

// ---------------- fused residual add + LayerNorm ---------------------------
__global__ void __launch_bounds__(128)
add_ln_kernel(const float* __restrict__ a, const float* __restrict__ r,
              const float* __restrict__ g, const float* __restrict__ bt,
              float* __restrict__ o) {
    int row = blockIdx.x;
    int tid = threadIdx.x;
    float v[3];
#pragma unroll
    for (int i = 0; i < 3; i++) {
        int e = tid + i * 128;
        v[i] = a[(size_t)row * EE + e] + r[(size_t)row * EE + e];
    }
    __shared__ float red[4];
    float s = v[0] + v[1] + v[2];
#pragma unroll
    for (int off = 16; off; off >>= 1) s += __shfl_xor_sync(~0u, s, off);
    if ((tid & 31) == 0) red[tid >> 5] = s;
    __syncthreads();
    float mean = (red[0] + red[1] + red[2] + red[3]) * (1.0f / EE);
    __syncthreads();
    float d0 = v[0] - mean, d1 = v[1] - mean, d2 = v[2] - mean;
    float sq = d0 * d0 + d1 * d1 + d2 * d2;
#pragma unroll
    for (int off = 16; off; off >>= 1) sq += __shfl_xor_sync(~0u, sq, off);
    if ((tid & 31) == 0) red[tid >> 5] = sq;
    __syncthreads();
    float var = (red[0] + red[1] + red[2] + red[3]) * (1.0f / EE);
    float inv = rsqrtf(var + 1e-5f);
#pragma unroll
    for (int i = 0; i < 3; i++) {
        int e = tid + i * 128;
        o[(size_t)row * EE + e] = (v[i] - mean) * inv * g[e] + bt[e];
    }
}

// ---------------- host orchestration ---------------------------------------
extern "C" void kernel_launch(void* const* d_in, const int* in_sizes, int n_in,
                              void* d_out, int out_size) {
    const float* enc = (const float*)d_in[0];
    const float* x   = (const float*)d_in[1];
    const float* sa1_wq = (const float*)d_in[2];
    const float* sa1_bq = (const float*)d_in[3];
    const float* sa1_wk = (const float*)d_in[4];
    const float* sa1_bk = (const float*)d_in[5];
    const float* sa1_wv = (const float*)d_in[6];
    const float* sa1_bv = (const float*)d_in[7];
    const float* sa1_pw = (const float*)d_in[8];
    const float* sa1_pb = (const float*)d_in[9];
    const float* sa2_wq = (const float*)d_in[10];
    const float* sa2_bq = (const float*)d_in[11];
    const float* sa2_wk = (const float*)d_in[12];
    const float* sa2_bk = (const float*)d_in[13];
    const float* sa2_wv = (const float*)d_in[14];
    const float* sa2_bv = (const float*)d_in[15];
    const float* sa2_pw = (const float*)d_in[16];
    const float* sa2_pb = (const float*)d_in[17];
    const float* ff_w1  = (const float*)d_in[18];
    const float* ff_b1  = (const float*)d_in[19];
    const float* ff_w2  = (const float*)d_in[20];
    const float* ff_b2  = (const float*)d_in[21];
    const float* ln1_g  = (const float*)d_in[22];
    const float* ln1_b  = (const float*)d_in[23];
    const float* ln2_g  = (const float*)d_in[24];
    const float* ln2_b  = (const float*)d_in[25];
    const float* ln3_g  = (const float*)d_in[26];
    const float* ln3_b  = (const float*)d_in[27];
    float* out = (float*)d_out;

    cudaFuncSetAttribute(attn_tc_kernel,
                         cudaFuncAttributeMaxDynamicSharedMemorySize, ATTN_SMEM);
    cudaFuncSetAttribute(gemm_tc_kernel,
                         cudaFuncAttributeMaxDynamicSharedMemorySize, GEMM_SMEM);

    float *pqkv, *pkv, *pq, *patt, *pbuf, *po1, *po2, *phid;
    float *pwqkv, *pwkv, *pwq, *pbqkv, *pbkv;
    cudaGetSymbolAddress((void**)&pqkv, g_qkv);
    cudaGetSymbolAddress((void**)&pkv,  g_kv);
    cudaGetSymbolAddress((void**)&pq,   g_q);
    cudaGetSymbolAddress((void**)&patt, g_att);
    cudaGetSymbolAddress((void**)&pbuf, g_buf);
    cudaGetSymbolAddress((void**)&po1,  g_o1);
    cudaGetSymbolAddress((void**)&po2,  g_o2);
    cudaGetSymbolAddress((void**)&phid, g_hidden);
    cudaGetSymbolAddress((void**)&pwqkv, g_wqkv);
    cudaGetSymbolAddress((void**)&pwkv,  g_wkv);
    cudaGetSymbolAddress((void**)&pwq,   g_wq);
    cudaGetSymbolAddress((void**)&pbqkv, g_bqkv);
    cudaGetSymbolAddress((void**)&pbkv,  g_bkv);

    const int PACK_BLOCKS = (HH * EE * HSS + 255) / 256;

    auto gemm = [&](const float* A, const float* W, const float* bias,
                    float* C, int K, int M, int relu) {
        dim3 grid(M / 128, NROWS / 128);
        gemm_tc_kernel<<<grid, 256, GEMM_SMEM>>>(A, W, bias, C, K, M, relu);
    };

    // ---- block 1: masked self-attention + add&norm ----
    pack_w_kernel<<<PACK_BLOCKS, 256>>>(sa1_wq, pwqkv, 3 * EE, 0);
    pack_w_kernel<<<PACK_BLOCKS, 256>>>(sa1_wk, pwqkv, 3 * EE, EE);
    pack_w_kernel<<<PACK_BLOCKS, 256>>>(sa1_wv, pwqkv, 3 * EE, 2 * EE);
    pack_bias_kernel<<<(3 * EE + 255) / 256, 256>>>(sa1_bq, sa1_bk, sa1_bv, pbqkv, EE, 3);
    gemm(x, pwqkv, pbqkv, pqkv, EE, 3 * EE, 0);
    attn_tc_kernel<<<BB * HH * 4, 256, ATTN_SMEM>>>(pqkv, 3 * EE,
                                                    pqkv + EE, pqkv + 2 * EE, 3 * EE, patt);
    gemm(patt, sa1_pw, sa1_pb, pbuf, EE, EE, 0);
    add_ln_kernel<<<NROWS, 128>>>(x, pbuf, ln1_g, ln1_b, po1);

    // ---- block 2: cross-attention (still causal-masked) + add&norm ----
    pack_w_kernel<<<PACK_BLOCKS, 256>>>(sa2_wq, pwq, EE, 0);
    pack_w_kernel<<<PACK_BLOCKS, 256>>>(sa2_wk, pwkv, 2 * EE, 0);
    pack_w_kernel<<<PACK_BLOCKS, 256>>>(sa2_wv, pwkv, 2 * EE, EE);
    pack_bias_kernel<<<(2 * EE + 255) / 256, 256>>>(sa2_bk, sa2_bv, sa2_bv, pbkv, EE, 2);
    gemm(po1, pwq, sa2_bq, pq, EE, EE, 0);
    gemm(enc, pwkv, pbkv, pkv, EE, 2 * EE, 0);
    attn_tc_kernel<<<BB * HH * 4, 256, ATTN_SMEM>>>(pq, EE,
                                                    pkv, pkv + EE, 2 * EE, patt);
    gemm(patt, sa2_pw, sa2_pb, pbuf, EE, EE, 0);
    add_ln_kernel<<<NROWS, 128>>>(po1, pbuf, ln2_g, ln2_b, po2);

    // ---- FFN + add&norm ----
    gemm(po2, ff_w1, ff_b1, phid, EE, FFD, 1);
    gemm(phid, ff_w2, ff_b2, pbuf, FFD, EE, 0);
    add_ln_kernel<<<NROWS, 128>>>(po2, pbuf, ln3_g, ln3_b, out);
}

// round 4
// speedup vs baseline: 3.7565x; 1.0441x over previous
#include <cuda_runtime.h>
#include <cstdint>
#include <cstddef>

// Problem constants
#define EE   384
#define HH   6
#define HSS  64
#define BB   64
#define TT   256
#define FFD  1536
#define NROWS (BB*TT)          // 16384

// ---------------- scratch (device globals; no allocation allowed) ----------
__device__ float g_qkv[(size_t)NROWS * 3 * EE];
__device__ float g_kv[(size_t)NROWS * 2 * EE];
__device__ float g_q[(size_t)NROWS * EE];
__device__ float g_att[(size_t)NROWS * EE];
__device__ float g_buf[(size_t)NROWS * EE];
__device__ float g_o1[(size_t)NROWS * EE];
__device__ float g_o2[(size_t)NROWS * EE];
__device__ float g_hidden[(size_t)NROWS * FFD];
__device__ float g_wqkv[EE * 3 * EE];
__device__ float g_wkv[EE * 2 * EE];
__device__ float g_wq[EE * EE];
__device__ float g_bqkv[3 * EE];
__device__ float g_bkv[2 * EE];

// ---------------- weight repack: [H,E,HS] -> row-major [E, ldo] at col0 ----
__global__ void pack_w_kernel(const float* __restrict__ w, float* __restrict__ o,
                              int ldo, int col0) {
    int idx = blockIdx.x * 256 + threadIdx.x;
    if (idx >= HH * EE * HSS) return;
    int h   = idx / (EE * HSS);
    int rem = idx % (EE * HSS);
    int e   = rem / HSS;
    int s   = rem % HSS;
    o[(size_t)e * ldo + col0 + h * HSS + s] = w[idx];
}

__global__ void pack_bias_kernel(const float* __restrict__ a,
                                 const float* __restrict__ b,
                                 const float* __restrict__ c,
                                 float* __restrict__ o, int n, int cnt) {
    int i = blockIdx.x * 256 + threadIdx.x;
    if (i >= n * cnt) return;
    if (i < n) o[i] = a[i];
    else if (i < 2 * n) o[i] = b[i - n];
    else o[i] = c[i - 2 * n];
}

// ---------------- TF32 tensor-core GEMM (3-stage, no explicit cvt) ---------
#define AS_STRIDE 36
#define BS_STRIDE 136
#define BUF_FLOATS (128*AS_STRIDE + 32*BS_STRIDE)     // 8960 floats
#define GEMM_SMEM (3 * BUF_FLOATS * 4)                // 107520 bytes

__device__ __forceinline__ void mma_tf32(float* c, const uint32_t* a, const uint32_t* b) {
    asm volatile(
        "mma.sync.aligned.m16n8k8.row.col.f32.tf32.tf32.f32 "
        "{%0,%1,%2,%3}, {%4,%5,%6,%7}, {%8,%9}, {%0,%1,%2,%3};"
        : "+f"(c[0]), "+f"(c[1]), "+f"(c[2]), "+f"(c[3])
        : "r"(a[0]), "r"(a[1]), "r"(a[2]), "r"(a[3]), "r"(b[0]), "r"(b[1]));
}
__device__ __forceinline__ void cp16(uint32_t dst, const void* src) {
    asm volatile("cp.async.cg.shared.global [%0], [%1], 16;" :: "r"(dst), "l"(src));
}
__device__ __forceinline__ uint32_t fbits(float f) { return __float_as_uint(f); }

__device__ __forceinline__ void load_tiles(uint32_t as_base, uint32_t bs_base,
                                           const float* __restrict__ A,
                                           const float* __restrict__ W,
                                           int row0, int col0, int kt,
                                           int K, int M, int tid) {
#pragma unroll
    for (int i = 0; i < 4; i++) {
        int li = tid + i * 256;
        int r = li >> 3, c4 = li & 7;
        cp16(as_base + (uint32_t)(r * AS_STRIDE + c4 * 4) * 4,
             A + (size_t)(row0 + r) * K + kt + c4 * 4);
    }
#pragma unroll
    for (int i = 0; i < 4; i++) {
        int li = tid + i * 256;
        int kr = li >> 5, c4 = li & 31;
        cp16(bs_base + (uint32_t)(kr * BS_STRIDE + c4 * 4) * 4,
             W + (size_t)(kt + kr) * M + col0 + c4 * 4);
    }
}

__global__ void __launch_bounds__(256, 2)
gemm_tc_kernel(const float* __restrict__ A, const float* __restrict__ W,
               const float* __restrict__ bias, float* __restrict__ C,
               int K, int M, int relu) {
    extern __shared__ float sm[];
    uint32_t as_u[3], bs_u[3];
    const float* Asb[3];
    const float* Bsb[3];
#pragma unroll
    for (int s = 0; s < 3; s++) {
        Asb[s] = sm + s * BUF_FLOATS;
        Bsb[s] = sm + s * BUF_FLOATS + 128 * AS_STRIDE;
        as_u[s] = (uint32_t)__cvta_generic_to_shared(Asb[s]);
        bs_u[s] = (uint32_t)__cvta_generic_to_shared(Bsb[s]);
    }

    int col0 = blockIdx.x * 128;
    int row0 = blockIdx.y * 128;
    int tid  = threadIdx.x;
    int lane = tid & 31, warp = tid >> 5;
    int wm = warp >> 2, wn = warp & 3;
    int gid = lane >> 2, tg = lane & 3;

    float acc[4][4][4];
#pragma unroll
    for (int i = 0; i < 4; i++)
#pragma unroll
        for (int j = 0; j < 4; j++)
#pragma unroll
            for (int r = 0; r < 4; r++) acc[i][j][r] = 0.0f;

    int nt_total = K >> 5;     // K/32 tiles
    load_tiles(as_u[0], bs_u[0], A, W, row0, col0, 0, K, M, tid);
    asm volatile("cp.async.commit_group;");
    if (nt_total > 1) {
        load_tiles(as_u[1], bs_u[1], A, W, row0, col0, 32, K, M, tid);
        asm volatile("cp.async.commit_group;");
    }

    for (int it = 0; it < nt_total; it++) {
        if (it + 1 < nt_total) asm volatile("cp.async.wait_group 1;");
        else                   asm volatile("cp.async.wait_group 0;");
        __syncthreads();
        if (it + 2 < nt_total) {
            int nb = (it + 2) % 3;
            load_tiles(as_u[nb], bs_u[nb], A, W, row0, col0, (it + 2) * 32, K, M, tid);
            asm volatile("cp.async.commit_group;");
        }
        const float* as = Asb[it % 3];
        const float* bs = Bsb[it % 3];
#pragma unroll
        for (int ks = 0; ks < 4; ks++) {
            int k0 = ks * 8;
            uint32_t af[4][4], bf[4][2];
#pragma unroll
            for (int mt = 0; mt < 4; mt++) {
                int ar = wm * 64 + mt * 16 + gid;
                af[mt][0] = fbits(as[ar * AS_STRIDE + k0 + tg]);
                af[mt][1] = fbits(as[(ar + 8) * AS_STRIDE + k0 + tg]);
                af[mt][2] = fbits(as[ar * AS_STRIDE + k0 + tg + 4]);
                af[mt][3] = fbits(as[(ar + 8) * AS_STRIDE + k0 + tg + 4]);
            }
#pragma unroll
            for (int nt = 0; nt < 4; nt++) {
                int bc = wn * 32 + nt * 8 + gid;
                bf[nt][0] = fbits(bs[(k0 + tg) * BS_STRIDE + bc]);
                bf[nt][1] = fbits(bs[(k0 + tg + 4) * BS_STRIDE + bc]);
            }
#pragma unroll
            for (int mt = 0; mt < 4; mt++)
#pragma unroll
                for (int nt = 0; nt < 4; nt++)
                    mma_tf32(acc[mt][nt], af[mt], bf[nt]);
        }
    }

#pragma unroll
    for (int mt = 0; mt < 4; mt++) {
#pragma unroll
        for (int nt = 0; nt < 4; nt++) {
            int r0 = row0 + wm * 64 + mt * 16 + gid;
            int c0 = col0 + wn * 32 + nt * 8 + tg * 2;
            float b0 = bias[c0], b1 = bias[c0 + 1];
            float v0 = acc[mt][nt][0] + b0;
            float v1 = acc[mt][nt][1] + b1;
            float v2 = acc[mt][nt][2] + b0;
            float v3 = acc[mt][nt][3] + b1;
            if (relu) {
                v0 = fmaxf(v0, 0.0f); v1 = fmaxf(v1, 0.0f);
                v2 = fmaxf(v2, 0.0f); v3 = fmaxf(v3, 0.0f);
            }
            C[(size_t)r0 * M + c0]           = v0;
            C[(size_t)r0 * M + c0 + 1]       = v1;
            C[(size_t)(r0 + 8) * M + c0]     = v2;
            C[(size_t)(r0 + 8) * M + c0 + 1] = v3;
        }
    }
}

// ---------------- tensor-core attention ------------------------------------
#define SQ_STR  68
#define SS_STR  260
#define ATTN_SMEM ((2*64*SQ_STR + 64*SS_STR) * 4)   // 101376 bytes

__global__ void __launch_bounds__(256, 2)
attn_tc_kernel(const float* __restrict__ Q, int ldq,
               const float* __restrict__ Kp, const float* __restrict__ Vp, int ldkv,
               float* __restrict__ O) {
    extern __shared__ float smn[];
    float* sQ  = smn;
    float* sKV = smn + 64 * SQ_STR;
    float* sS  = smn + 2 * 64 * SQ_STR;

    int bid  = blockIdx.x;
    int tile = bid & 3;
    int h    = (bid >> 2) % HH;
    int b    = bid / (4 * HH);
    int t0   = tile * 64;
    int tid  = threadIdx.x;
    int lane = tid & 31, warp = tid >> 5;
    int wm = warp >> 1, wn = warp & 1;
    int gid = lane >> 2, tg = lane & 3;
    int am = wm * 16;

    size_t qbase = (size_t)(b * TT + t0) * ldq + h * HSS;
#pragma unroll
    for (int i = 0; i < 16; i++) {
        int lin = tid + i * 256;
        int ti = lin >> 6, s = lin & 63;
        sQ[ti * SQ_STR + s] = Q[qbase + (size_t)ti * ldq + s];
    }

    const float scale = rsqrtf((float)EE);

    for (int ut = 0; ut <= tile; ut++) {
        size_t kbase = (size_t)(b * TT + ut * 64) * ldkv + h * HSS;
        __syncthreads();
#pragma unroll
        for (int i = 0; i < 16; i++) {
            int lin = tid + i * 256;
            int ui = lin >> 6, s = lin & 63;
            sKV[ui * SQ_STR + s] = Kp[kbase + (size_t)ui * ldkv + s];
        }
        __syncthreads();
        float acc[4][4] = {};
#pragma unroll
        for (int ks = 0; ks < 8; ks++) {
            int k0 = ks * 8;
            uint32_t af[4];
            af[0] = fbits(sQ[(am + gid) * SQ_STR + k0 + tg]);
            af[1] = fbits(sQ[(am + gid + 8) * SQ_STR + k0 + tg]);
            af[2] = fbits(sQ[(am + gid) * SQ_STR + k0 + tg + 4]);
            af[3] = fbits(sQ[(am + gid + 8) * SQ_STR + k0 + tg + 4]);
#pragma unroll
            for (int nt = 0; nt < 4; nt++) {
                int n = wn * 32 + nt * 8 + gid;
                uint32_t bf[2];
                bf[0] = fbits(sKV[n * SQ_STR + k0 + tg]);
                bf[1] = fbits(sKV[n * SQ_STR + k0 + tg + 4]);
                mma_tf32(acc[nt], af, bf);
            }
        }
#pragma unroll
        for (int nt = 0; nt < 4; nt++) {
            int c0 = ut * 64 + wn * 32 + nt * 8 + tg * 2;
            sS[(am + gid) * SS_STR + c0]         = acc[nt][0] * scale;
            sS[(am + gid) * SS_STR + c0 + 1]     = acc[nt][1] * scale;
            sS[(am + gid + 8) * SS_STR + c0]     = acc[nt][2] * scale;
            sS[(am + gid + 8) * SS_STR + c0 + 1] = acc[nt][3] * scale;
        }
    }
    __syncthreads();

    {
        int row = tid >> 2, tg4 = tid & 3;
        int nvalid = t0 + row + 1;
        int ncomp  = (tile + 1) * 64;
        float m = -1e30f;
        for (int u = tg4; u < nvalid; u += 4)
            m = fmaxf(m, sS[row * SS_STR + u]);
        m = fmaxf(m, __shfl_xor_sync(~0u, m, 1));
        m = fmaxf(m, __shfl_xor_sync(~0u, m, 2));
        float sum = 0.0f;
        for (int u = tg4; u < ncomp; u += 4) {
            float e = (u < nvalid) ? __expf(sS[row * SS_STR + u] - m) : 0.0f;
            sS[row * SS_STR + u] = e;
            sum += e;
        }
        sum += __shfl_xor_sync(~0u, sum, 1);
        sum += __shfl_xor_sync(~0u, sum, 2);
        float inv = 1.0f / sum;
        for (int u = tg4; u < ncomp; u += 4)
            sS[row * SS_STR + u] *= inv;
    }

    float acc2[4][4] = {};
    for (int ut = 0; ut <= tile; ut++) {
        size_t vbase = (size_t)(b * TT + ut * 64) * ldkv + h * HSS;
        __syncthreads();
#pragma unroll
        for (int i = 0; i < 16; i++) {
            int lin = tid + i * 256;
            int ui = lin >> 6, s = lin & 63;
            sKV[s * SQ_STR + ui] = Vp[vbase + (size_t)ui * ldkv + s];
        }
        __syncthreads();
#pragma unroll
        for (int ks = 0; ks < 8; ks++) {
            int k0 = ks * 8;
            uint32_t af[4];
            af[0] = fbits(sS[(am + gid) * SS_STR + ut * 64 + k0 + tg]);
            af[1] = fbits(sS[(am + gid + 8) * SS_STR + ut * 64 + k0 + tg]);
            af[2] = fbits(sS[(am + gid) * SS_STR + ut * 64 + k0 + tg + 4]);
            af[3] = fbits(sS[(am + gid + 8) * SS_STR + ut * 64 + k0 + tg + 4]);
#pragma unroll
            for (int nt = 0; nt < 4; nt++) {
                int n = wn * 32 + nt * 8 + gid;
                uint32_t bf[2];
                bf[0] = fbits(sKV[n * SQ_STR + k0 + tg]);
                bf[1] = fbits(sKV[n * SQ_STR + k0 + tg + 4]);
                mma_tf32(acc2[nt], af, bf);
            }
        }
    }
    size_t obase = (size_t)(b * TT + t0) * EE + h * HSS;
#pragma unroll
    for (int nt = 0; nt < 4; nt++) {
        int c0 = wn * 32 + nt * 8 + tg * 2;
        O[obase + (size_t)(am + gid) * EE + c0]         = acc2[nt][0];
        O[obase + (size_t)(am + gid) * EE + c0 + 1]     = acc2[nt][1];
        O[obase + (size_t)(am + gid + 8) * EE + c0]     = acc2[nt][2];
        O[obase + (size_t)(am + gid + 8) * EE + c0 + 1] = acc2[nt][3];
    }
}

// ---------------- fused residual add + LayerNorm ---------------------------
__global__ void __launch_bounds__(128)
add_ln_kernel(const float* __restrict__ a, const float* __restrict__ r,
              const float* __restrict__ g, const float* __restrict__ bt,
              float* __restrict__ o) {
    int row = blockIdx.x;
    int tid = threadIdx.x;
    float v[3];
#pragma unroll
    for (int i = 0; i < 3; i++) {
        int e = tid + i * 128;
        v[i] = a[(size_t)row * EE + e] + r[(size_t)row * EE + e];
    }
    __shared__ float red[4];
    float s = v[0] + v[1] + v[2];
#pragma unroll
    for (int off = 16; off; off >>= 1) s += __shfl_xor_sync(~0u, s, off);
    if ((tid & 31) == 0) red[tid >> 5] = s;
    __syncthreads();
    float mean = (red[0] + red[1] + red[2] + red[3]) * (1.0f / EE);
    __syncthreads();
    float d0 = v[0] - mean, d1 = v[1] - mean, d2 = v[2] - mean;
    float sq = d0 * d0 + d1 * d1 + d2 * d2;
#pragma unroll
    for (int off = 16; off; off >>= 1) sq += __shfl_xor_sync(~0u, sq, off);
    if ((tid & 31) == 0) red[tid >> 5] = sq;
    __syncthreads();
    float var = (red[0] + red[1] + red[2] + red[3]) * (1.0f / EE);
    float inv = rsqrtf(var + 1e-5f);
#pragma unroll
    for (int i = 0; i < 3; i++) {
        int e = tid + i * 128;
        o[(size_t)row * EE + e] = (v[i] - mean) * inv * g[e] + bt[e];
    }
}

// ---------------- host orchestration ---------------------------------------
extern "C" void kernel_launch(void* const* d_in, const int* in_sizes, int n_in,
                              void* d_out, int out_size) {
    const float* enc = (const float*)d_in[0];
    const float* x   = (const float*)d_in[1];
    const float* sa1_wq = (const float*)d_in[2];
    const float* sa1_bq = (const float*)d_in[3];
    const float* sa1_wk = (const float*)d_in[4];
    const float* sa1_bk = (const float*)d_in[5];
    const float* sa1_wv = (const float*)d_in[6];
    const float* sa1_bv = (const float*)d_in[7];
    const float* sa1_pw = (const float*)d_in[8];
    const float* sa1_pb = (const float*)d_in[9];
    const float* sa2_wq = (const float*)d_in[10];
    const float* sa2_bq = (const float*)d_in[11];
    const float* sa2_wk = (const float*)d_in[12];
    const float* sa2_bk = (const float*)d_in[13];
    const float* sa2_wv = (const float*)d_in[14];
    const float* sa2_bv = (const float*)d_in[15];
    const float* sa2_pw = (const float*)d_in[16];
    const float* sa2_pb = (const float*)d_in[17];
    const float* ff_w1  = (const float*)d_in[18];
    const float* ff_b1  = (const float*)d_in[19];
    const float* ff_w2  = (const float*)d_in[20];
    const float* ff_b2  = (const float*)d_in[21];
    const float* ln1_g  = (const float*)d_in[22];
    const float* ln1_b  = (const float*)d_in[23];
    const float* ln2_g  = (const float*)d_in[24];
    const float* ln2_b  = (const float*)d_in[25];
    const float* ln3_g  = (const float*)d_in[26];
    const float* ln3_b  = (const float*)d_in[27];
    float* out = (float*)d_out;

    cudaFuncSetAttribute(attn_tc_kernel,
                         cudaFuncAttributeMaxDynamicSharedMemorySize, ATTN_SMEM);
    cudaFuncSetAttribute(gemm_tc_kernel,
                         cudaFuncAttributeMaxDynamicSharedMemorySize, GEMM_SMEM);

    float *pqkv, *pkv, *pq, *patt, *pbuf, *po1, *po2, *phid;
    float *pwqkv, *pwkv, *pwq, *pbqkv, *pbkv;
    cudaGetSymbolAddress((void**)&pqkv, g_qkv);
    cudaGetSymbolAddress((void**)&pkv,  g_kv);
    cudaGetSymbolAddress((void**)&pq,   g_q);
    cudaGetSymbolAddress((void**)&patt, g_att);
    cudaGetSymbolAddress((void**)&pbuf, g_buf);
    cudaGetSymbolAddress((void**)&po1,  g_o1);
    cudaGetSymbolAddress((void**)&po2,  g_o2);
    cudaGetSymbolAddress((void**)&phid, g_hidden);
    cudaGetSymbolAddress((void**)&pwqkv, g_wqkv);
    cudaGetSymbolAddress((void**)&pwkv,  g_wkv);
    cudaGetSymbolAddress((void**)&pwq,   g_wq);
    cudaGetSymbolAddress((void**)&pbqkv, g_bqkv);
    cudaGetSymbolAddress((void**)&pbkv,  g_bkv);

    const int PACK_BLOCKS = (HH * EE * HSS + 255) / 256;

    auto gemm = [&](const float* A, const float* W, const float* bias,
                    float* C, int K, int M, int relu) {
        dim3 grid(M / 128, NROWS / 128);
        gemm_tc_kernel<<<grid, 256, GEMM_SMEM>>>(A, W, bias, C, K, M, relu);
    };

    // ---- block 1: masked self-attention + add&norm ----
    pack_w_kernel<<<PACK_BLOCKS, 256>>>(sa1_wq, pwqkv, 3 * EE, 0);
    pack_w_kernel<<<PACK_BLOCKS, 256>>>(sa1_wk, pwqkv, 3 * EE, EE);
    pack_w_kernel<<<PACK_BLOCKS, 256>>>(sa1_wv, pwqkv, 3 * EE, 2 * EE);
    pack_bias_kernel<<<(3 * EE + 255) / 256, 256>>>(sa1_bq, sa1_bk, sa1_bv, pbqkv, EE, 3);
    gemm(x, pwqkv, pbqkv, pqkv, EE, 3 * EE, 0);
    attn_tc_kernel<<<BB * HH * 4, 256, ATTN_SMEM>>>(pqkv, 3 * EE,
                                                    pqkv + EE, pqkv + 2 * EE, 3 * EE, patt);
    gemm(patt, sa1_pw, sa1_pb, pbuf, EE, EE, 0);
    add_ln_kernel<<<NROWS, 128>>>(x, pbuf, ln1_g, ln1_b, po1);

    // ---- block 2: cross-attention (still causal-masked) + add&norm ----
    pack_w_kernel<<<PACK_BLOCKS, 256>>>(sa2_wq, pwq, EE, 0);
    pack_w_kernel<<<PACK_BLOCKS, 256>>>(sa2_wk, pwkv, 2 * EE, 0);
    pack_w_kernel<<<PACK_BLOCKS, 256>>>(sa2_wv, pwkv, 2 * EE, EE);
    pack_bias_kernel<<<(2 * EE + 255) / 256, 256>>>(sa2_bk, sa2_bv, sa2_bv, pbkv, EE, 2);
    gemm(po1, pwq, sa2_bq, pq, EE, EE, 0);
    gemm(enc, pwkv, pbkv, pkv, EE, 2 * EE, 0);
    attn_tc_kernel<<<BB * HH * 4, 256, ATTN_SMEM>>>(pq, EE,
                                                    pkv, pkv + EE, 2 * EE, patt);
    gemm(patt, sa2_pw, sa2_pb, pbuf, EE, EE, 0);
    add_ln_kernel<<<NROWS, 128>>>(po1, pbuf, ln2_g, ln2_b, po2);

    // ---- FFN + add&norm ----
    gemm(po2, ff_w1, ff_b1, phid, EE, FFD, 1);
    gemm(phid, ff_w2, ff_b2, pbuf, FFD, EE, 0);
    add_ln_kernel<<<NROWS, 128>>>(po2, pbuf, ln3_g, ln3_b, out);
}

// round 6
// speedup vs baseline: 8.9035x; 2.3702x over previous
#include <cuda_runtime.h>
#include <cuda_fp16.h>
#include <cstdint>
#include <cstddef>

// Problem constants
#define EE   384
#define HH   6
#define HSS  64
#define BB   64
#define TT   256
#define FFD  1536
#define NROWS (BB*TT)          // 16384

// ---------------- scratch (device globals; no allocation allowed) ----------
__device__ __half g_qkv_h[(size_t)NROWS * 3 * EE];
__device__ __half g_kv_h[(size_t)NROWS * 2 * EE];
__device__ __half g_q_h[(size_t)NROWS * EE];
__device__ __half g_att_h[(size_t)NROWS * EE];
__device__ __half g_hid_h[(size_t)NROWS * FFD];
__device__ __half g_xh[(size_t)NROWS * EE];
__device__ __half g_ench[(size_t)NROWS * EE];
__device__ __half g_po1h[(size_t)NROWS * EE];
__device__ __half g_po2h[(size_t)NROWS * EE];
__device__ float  g_buf[(size_t)NROWS * EE];
__device__ float  g_o1[(size_t)NROWS * EE];
__device__ float  g_o2[(size_t)NROWS * EE];
// fp16 weights, transposed to [out][in]
__device__ __half g_wqkvh[3 * EE * EE];
__device__ __half g_wq2h[EE * EE];
__device__ __half g_wkvh[2 * EE * EE];
__device__ __half g_wp1h[EE * EE];
__device__ __half g_wp2h[EE * EE];
__device__ __half g_wf1h[FFD * EE];
__device__ __half g_wf2h[EE * FFD];
__device__ float  g_bqkv[3 * EE];
__device__ float  g_bkv[2 * EE];
__device__ float  g_bq2[EE];

// ---------------- PTX helpers ----------------------------------------------
__device__ __forceinline__ uint32_t smem_u32(const void* p) {
    uint32_t a;
    asm("{ .reg .u64 t; cvta.to.shared.u64 t, %1; cvt.u32.u64 %0, t; }" : "=r"(a) : "l"(p));
    return a;
}
__device__ __forceinline__ void cp16(uint32_t dst, const void* src) {
    asm volatile("cp.async.cg.shared.global [%0], [%1], 16;" :: "r"(dst), "l"(src));
}
__device__ __forceinline__ void ldsm4(uint32_t& r0, uint32_t& r1, uint32_t& r2, uint32_t& r3,
                                      uint32_t addr) {
    asm volatile("ldmatrix.sync.aligned.m8n8.x4.shared.b16 {%0,%1,%2,%3}, [%4];"
                 : "=r"(r0), "=r"(r1), "=r"(r2), "=r"(r3) : "r"(addr));
}
__device__ __forceinline__ void ldsm4t(uint32_t& r0, uint32_t& r1, uint32_t& r2, uint32_t& r3,
                                       uint32_t addr) {
    asm volatile("ldmatrix.sync.aligned.m8n8.x4.trans.shared.b16 {%0,%1,%2,%3}, [%4];"
                 : "=r"(r0), "=r"(r1), "=r"(r2), "=r"(r3) : "r"(addr));
}
__device__ __forceinline__ void mma16816(float* c, const uint32_t* a, const uint32_t* b) {
    asm volatile(
        "mma.sync.aligned.m16n8k16.row.col.f32.f16.f16.f32 "
        "{%0,%1,%2,%3}, {%4,%5,%6,%7}, {%8,%9}, {%0,%1,%2,%3};"
        : "+f"(c[0]), "+f"(c[1]), "+f"(c[2]), "+f"(c[3])
        : "r"(a[0]), "r"(a[1]), "r"(a[2]), "r"(a[3]), "r"(b[0]), "r"(b[1]));
}
__device__ __forceinline__ uint32_t ph2(float a, float b) {
    __half2 h = __floats2half2_rn(a, b);
    return *reinterpret_cast<uint32_t*>(&h);
}
// swizzled byte offset within a tile of 128B rows (64 halfs/row), seg = 16B unit
__device__ __forceinline__ uint32_t sw_off(int r, int seg) {
    return (uint32_t)(r * 128 + (((seg ^ (r & 7)) & 7) << 4));
}

// ---------------- megapack: weights -> fp16 [out][in], biases, activations -
#define HPK 147456
#define S_ATTNW (6*HPK)
#define S_PROJ  (2*HPK)
#define S_FF    (EE*FFD)
#define NACT    ((size_t)NROWS*EE)
#define PACK_TOTAL (S_ATTNW + S_PROJ + 2*S_FF + 3*EE + 2*EE + EE + 2*(int)NACT)

__global__ void megapack_kernel(
    const float* __restrict__ wq1, const float* __restrict__ wk1, const float* __restrict__ wv1,
    const float* __restrict__ wq2, const float* __restrict__ wk2, const float* __restrict__ wv2,
    const float* __restrict__ pw1, const float* __restrict__ pw2,
    const float* __restrict__ fw1, const float* __restrict__ fw2,
    const float* __restrict__ bq1, const float* __restrict__ bk1, const float* __restrict__ bv1,
    const float* __restrict__ bq2, const float* __restrict__ bk2, const float* __restrict__ bv2,
    const float* __restrict__ x, const float* __restrict__ enc,
    __half* __restrict__ wqkv, __half* __restrict__ wqo, __half* __restrict__ wkv,
    __half* __restrict__ wp1o, __half* __restrict__ wp2o,
    __half* __restrict__ wf1o, __half* __restrict__ wf2o,
    float* __restrict__ bqkv, float* __restrict__ bkv, float* __restrict__ bq2o,
    __half* __restrict__ xh, __half* __restrict__ ench)
{
    long long idx = (long long)blockIdx.x * 256 + threadIdx.x;
    if (idx >= PACK_TOTAL) return;
    const float scale = rsqrtf((float)EE);
    if (idx < S_ATTNW) {
        int reg = (int)(idx / HPK), i = (int)(idx % HPK);
        int h = i / (EE * HSS), e = (i / HSS) % EE, s = i % HSS;
        int out = h * HSS + s;
        float v; __half* dst; int rowoff;
        switch (reg) {
            case 0: v = wq1[i] * scale; dst = wqkv; rowoff = 0;      break;
            case 1: v = wk1[i];         dst = wqkv; rowoff = EE;     break;
            case 2: v = wv1[i];         dst = wqkv; rowoff = 2 * EE; break;
            case 3: v = wq2[i] * scale; dst = wqo;  rowoff = 0;      break;
            case 4: v = wk2[i];         dst = wkv;  rowoff = 0;      break;
            default: v = wv2[i];        dst = wkv;  rowoff = EE;     break;
        }
        dst[(size_t)(rowoff + out) * EE + e] = __float2half_rn(v);
        return;
    }
    idx -= S_ATTNW;
    if (idx < S_PROJ) {
        int reg = (int)(idx / HPK), i = (int)(idx % HPK);
        int e = i / EE, o = i % EE;
        (reg ? wp2o : wp1o)[(size_t)o * EE + e] = __float2half_rn((reg ? pw2 : pw1)[i]);
        return;
    }
    idx -= S_PROJ;
    if (idx < S_FF) {
        int e = (int)(idx / FFD), o = (int)(idx % FFD);
        wf1o[(size_t)o * EE + e] = __float2half_rn(fw1[idx]);
        return;
    }
    idx -= S_FF;
    if (idx < S_FF) {
        int e = (int)(idx / EE), o = (int)(idx % EE);
        wf2o[(size_t)o * FFD + e] = __float2half_rn(fw2[idx]);
        return;
    }
    idx -= S_FF;
    if (idx < 3 * EE) {
        int sub = (int)(idx / EE), jj = (int)(idx % EE);
        bqkv[idx] = sub == 0 ? bq1[jj] * scale : sub == 1 ? bk1[jj] : bv1[jj];
        return;
    }
    idx -= 3 * EE;
    if (idx < 2 * EE) { bkv[idx] = idx < EE ? bk2[idx] : bv2[idx - EE]; return; }
    idx -= 2 * EE;
    if (idx < EE) { bq2o[idx] = bq2[idx] * scale; return; }
    idx -= EE;
    if (idx < (long long)NACT) { xh[idx] = __float2half_rn(x[idx]); return; }
    idx -= NACT;
    ench[idx] = __float2half_rn(enc[idx]);
}

// ---------------- fp16 tensor-core GEMM ------------------------------------
// C[N,M] = A[N,K] @ Wt[M,K]^T + bias (opt relu). 128x128 tile, BK=64, 3-stage.
#define G16_SMEM (3 * 32768)

__global__ void __launch_bounds__(256, 2)
gemm16_kernel(const __half* __restrict__ A, const __half* __restrict__ Wt,
              const float* __restrict__ bias, float* __restrict__ Cf,
              __half* __restrict__ Ch, int K, int M, int relu)
{
    extern __shared__ __align__(128) char gsm[];
    uint32_t sbase = smem_u32(gsm);
    int tid = threadIdx.x, lane = tid & 31, warp = tid >> 5;
    int wm = warp >> 2, wn = warp & 3;
    int gid = lane >> 2, tg = lane & 3;
    int j = lane >> 3, rr = lane & 7;
    int col0 = blockIdx.x * 128, row0 = blockIdx.y * 128;

    float acc[4][4][4];
#pragma unroll
    for (int a = 0; a < 4; a++)
#pragma unroll
        for (int b = 0; b < 4; b++)
#pragma unroll
            for (int c = 0; c < 4; c++) acc[a][b][c] = 0.0f;

    int nch = K >> 6;
#define LOADC(stage, kt)                                                          \
    {                                                                             \
        uint32_t sA = sbase + (uint32_t)(stage) * 32768u;                         \
        uint32_t sB = sA + 16384u;                                                \
        _Pragma("unroll")                                                         \
        for (int i = 0; i < 4; i++) {                                             \
            int li = tid + i * 256; int r = li >> 3, sg = li & 7;                 \
            cp16(sA + sw_off(r, sg), A  + (size_t)(row0 + r) * K + (kt) + sg * 8);\
            cp16(sB + sw_off(r, sg), Wt + (size_t)(col0 + r) * K + (kt) + sg * 8);\
        }                                                                         \
        asm volatile("cp.async.commit_group;");                                   \
    }

    LOADC(0, 0);
    LOADC(1, 64);

    for (int it = 0; it < nch; it++) {
        if (it + 1 < nch) asm volatile("cp.async.wait_group 1;");
        else              asm volatile("cp.async.wait_group 0;");
        __syncthreads();
        if (it + 2 < nch) LOADC((it + 2) % 3, (it + 2) * 64);
        uint32_t sA = sbase + (uint32_t)(it % 3) * 32768u;
        uint32_t sB = sA + 16384u;
#pragma unroll
        for (int ks = 0; ks < 4; ks++) {
            uint32_t a[4][4], bfr[2][4];
#pragma unroll
            for (int mt = 0; mt < 4; mt++)
                ldsm4(a[mt][0], a[mt][1], a[mt][2], a[mt][3],
                      sA + sw_off(wm * 64 + mt * 16 + (j & 1) * 8 + rr, ks * 2 + (j >> 1)));
#pragma unroll
            for (int p = 0; p < 2; p++)
                ldsm4(bfr[p][0], bfr[p][1], bfr[p][2], bfr[p][3],
                      sB + sw_off(wn * 32 + p * 16 + (j >> 1) * 8 + rr, ks * 2 + (j & 1)));
#pragma unroll
            for (int mt = 0; mt < 4; mt++)
#pragma unroll
                for (int nt = 0; nt < 4; nt++)
                    mma16816(acc[mt][nt], a[mt], &bfr[nt >> 1][(nt & 1) * 2]);
        }
    }

#pragma unroll
    for (int mt = 0; mt < 4; mt++)
#pragma unroll
        for (int nt = 0; nt < 4; nt++) {
            int r0 = row0 + wm * 64 + mt * 16 + gid;
            int c0 = col0 + wn * 32 + nt * 8 + tg * 2;
            float b0 = bias[c0], b1 = bias[c0 + 1];
            float v0 = acc[mt][nt][0] + b0, v1 = acc[mt][nt][1] + b1;
            float v2 = acc[mt][nt][2] + b0, v3 = acc[mt][nt][3] + b1;
            if (relu) {
                v0 = fmaxf(v0, 0.f); v1 = fmaxf(v1, 0.f);
                v2 = fmaxf(v2, 0.f); v3 = fmaxf(v3, 0.f);
            }
            if (Cf) {
                *(float2*)(Cf + (size_t)r0 * M + c0)       = make_float2(v0, v1);
                *(float2*)(Cf + (size_t)(r0 + 8) * M + c0) = make_float2(v2, v3);
            }
            if (Ch) {
                *(__half2*)(Ch + (size_t)r0 * M + c0)       = __floats2half2_rn(v0, v1);
                *(__half2*)(Ch + (size_t)(r0 + 8) * M + c0) = __floats2half2_rn(v2, v3);
            }
        }
}

// ---------------- flash attention, fp16 mma, online softmax ----------------
// One CTA (128 thr, 4 warps) per (b, h, 64-query tile). Causal. Scale folded
// into Q projection weights. Q/K/V half, swizzled 128B rows in smem.
#define AT_SMEM (8192 + 4 * 8192)     // sQ + double-buffered K,V

__global__ void __launch_bounds__(128)
attn16_kernel(const __half* __restrict__ Qg, int ldq,
              const __half* __restrict__ Kg, const __half* __restrict__ Vg, int ldkv,
              __half* __restrict__ Og)
{
    extern __shared__ __align__(128) char asmem[];
    uint32_t sbase = smem_u32(asmem);
    uint32_t sQ = sbase;
    int tid = threadIdx.x, lane = tid & 31, w = tid >> 5;
    int gid = lane >> 2, tg = lane & 3;
    int j = lane >> 3, rr = lane & 7;

    int bid = blockIdx.x;
    int tile = bid & 3, h = (bid >> 2) % HH, b = bid / (4 * HH);
    int t0 = tile * 64;
    int hoff = h * HSS;

    const __half* qrow = Qg + (size_t)(b * TT + t0) * ldq + hoff;
#pragma unroll
    for (int i = 0; i < 4; i++) {
        int li = tid + i * 128; int r = li >> 3, sg = li & 7;
        cp16(sQ + sw_off(r, sg), qrow + (size_t)r * ldq + sg * 8);
    }
#define KVLOAD(ut, bufi)                                                           \
    {                                                                              \
        uint32_t sK_ = sbase + 8192u + (uint32_t)(bufi) * 16384u;                  \
        uint32_t sV_ = sK_ + 8192u;                                                \
        const __half* kr = Kg + (size_t)(b * TT + (ut) * 64) * ldkv + hoff;        \
        const __half* vr = Vg + (size_t)(b * TT + (ut) * 64) * ldkv + hoff;        \
        _Pragma("unroll")                                                          \
        for (int i = 0; i < 4; i++) {                                              \
            int li = tid + i * 128; int r = li >> 3, sg = li & 7;                  \
            cp16(sK_ + sw_off(r, sg), kr + (size_t)r * ldkv + sg * 8);             \
            cp16(sV_ + sw_off(r, sg), vr + (size_t)r * ldkv + sg * 8);             \
        }                                                                          \
        asm volatile("cp.async.commit_group;");                                    \
    }
    KVLOAD(0, 0);
    asm volatile("cp.async.wait_group 0;");
    __syncthreads();

    uint32_t qf[4][4];
#pragma unroll
    for (int ks = 0; ks < 4; ks++)
        ldsm4(qf[ks][0], qf[ks][1], qf[ks][2], qf[ks][3],
              sQ + sw_off(w * 16 + (j & 1) * 8 + rr, ks * 2 + (j >> 1)));

    float o[8][4];
#pragma unroll
    for (int nt = 0; nt < 8; nt++)
#pragma unroll
        for (int e = 0; e < 4; e++) o[nt][e] = 0.0f;
    float m0 = -1e30f, m1 = -1e30f, l0 = 0.0f, l1 = 0.0f;

    for (int ut = 0; ut <= tile; ut++) {
        if (ut > 0) { asm volatile("cp.async.wait_group 0;"); __syncthreads(); }
        if (ut < tile) KVLOAD(ut + 1, (ut + 1) & 1);
        uint32_t sK = sbase + 8192u + (uint32_t)(ut & 1) * 16384u;
        uint32_t sV = sK + 8192u;

        float s[8][4];
#pragma unroll
        for (int nt = 0; nt < 8; nt++)
#pragma unroll
            for (int e = 0; e < 4; e++) s[nt][e] = 0.0f;
#pragma unroll
        for (int ks = 0; ks < 4; ks++) {
            uint32_t kb[4][4];
#pragma unroll
            for (int p = 0; p < 4; p++)
                ldsm4(kb[p][0], kb[p][1], kb[p][2], kb[p][3],
                      sK + sw_off(p * 16 + (j >> 1) * 8 + rr, ks * 2 + (j & 1)));
#pragma unroll
            for (int nt = 0; nt < 8; nt++)
                mma16816(s[nt], qf[ks], &kb[nt >> 1][(nt & 1) * 2]);
        }
        if (ut == tile) {
            int r0l = w * 16 + gid;
#pragma unroll
            for (int nt = 0; nt < 8; nt++) {
                int u0 = nt * 8 + tg * 2;
                if (u0     > r0l)     s[nt][0] = -1e30f;
                if (u0 + 1 > r0l)     s[nt][1] = -1e30f;
                if (u0     > r0l + 8) s[nt][2] = -1e30f;
                if (u0 + 1 > r0l + 8) s[nt][3] = -1e30f;
            }
        }
        float mx0 = -1e30f, mx1 = -1e30f;
#pragma unroll
        for (int nt = 0; nt < 8; nt++) {
            mx0 = fmaxf(mx0, fmaxf(s[nt][0], s[nt][1]));
            mx1 = fmaxf(mx1, fmaxf(s[nt][2], s[nt][3]));
        }
        mx0 = fmaxf(mx0, __shfl_xor_sync(~0u, mx0, 1));
        mx0 = fmaxf(mx0, __shfl_xor_sync(~0u, mx0, 2));
        mx1 = fmaxf(mx1, __shfl_xor_sync(~0u, mx1, 1));
        mx1 = fmaxf(mx1, __shfl_xor_sync(~0u, mx1, 2));
        float mn0 = fmaxf(m0, mx0), mn1 = fmaxf(m1, mx1);
        float f0 = __expf(m0 - mn0), f1 = __expf(m1 - mn1);
        m0 = mn0; m1 = mn1;
        float rs0 = 0.0f, rs1 = 0.0f;
#pragma unroll
        for (int nt = 0; nt < 8; nt++) {
            s[nt][0] = __expf(s[nt][0] - mn0); rs0 += s[nt][0];
            s[nt][1] = __expf(s[nt][1] - mn0); rs0 += s[nt][1];
            s[nt][2] = __expf(s[nt][2] - mn1); rs1 += s[nt][2];
            s[nt][3] = __expf(s[nt][3] - mn1); rs1 += s[nt][3];
        }
        rs0 += __shfl_xor_sync(~0u, rs0, 1); rs0 += __shfl_xor_sync(~0u, rs0, 2);
        rs1 += __shfl_xor_sync(~0u, rs1, 1); rs1 += __shfl_xor_sync(~0u, rs1, 2);
        l0 = l0 * f0 + rs0;
        l1 = l1 * f1 + rs1;
#pragma unroll
        for (int nt = 0; nt < 8; nt++) {
            o[nt][0] *= f0; o[nt][1] *= f0; o[nt][2] *= f1; o[nt][3] *= f1;
        }
        uint32_t pa[4][4];
#pragma unroll
        for (int kk = 0; kk < 4; kk++) {
            pa[kk][0] = ph2(s[2 * kk][0], s[2 * kk][1]);
            pa[kk][1] = ph2(s[2 * kk][2], s[2 * kk][3]);
            pa[kk][2] = ph2(s[2 * kk + 1][0], s[2 * kk + 1][1]);
            pa[kk][3] = ph2(s[2 * kk + 1][2], s[2 * kk + 1][3]);
        }
#pragma unroll
        for (int kk = 0; kk < 4; kk++) {
            uint32_t vb[4][4];
#pragma unroll
            for (int p = 0; p < 4; p++)
                ldsm4t(vb[p][0], vb[p][1], vb[p][2], vb[p][3],
                       sV + sw_off(kk * 16 + (j & 1) * 8 + rr, p * 2 + (j >> 1)));
#pragma unroll
            for (int nt = 0; nt < 8; nt++)
                mma16816(o[nt], pa[kk], &vb[nt >> 1][(nt & 1) * 2]);
        }
    }
    float i0 = 1.0f / l0, i1 = 1.0f / l1;
    __half* orow = Og + (size_t)(b * TT + t0) * EE + hoff;
#pragma unroll
    for (int nt = 0; nt < 8; nt++) {
        int c = nt * 8 + tg * 2;
        *(__half2*)(orow + (size_t)(w * 16 + gid) * EE + c) =
            __floats2half2_rn(o[nt][0] * i0, o[nt][1] * i0);
        *(__half2*)(orow + (size_t)(w * 16 + gid + 8) * EE + c) =
            __floats2half2_rn(o[nt][2] * i1, o[nt][3] * i1);
    }
}

// ---------------- fused residual add + LayerNorm (+optional half copy) -----
__global__ void __launch_bounds__(128)
add_ln_kernel(const float* __restrict__ a, const float* __restrict__ r,
              const float* __restrict__ g, const float* __restrict__ bt,
              float* __restrict__ o, __half* __restrict__ oh) {
    int row = blockIdx.x;
    int tid = threadIdx.x;
    float v[3];
#pragma unroll
    for (int i = 0; i < 3; i++) {
        int e = tid + i * 128;
        v[i] = a[(size_t)row * EE + e] + r[(size_t)row * EE + e];
    }
    __shared__ float red[4];
    float s = v[0] + v[1] + v[2];
#pragma unroll
    for (int off = 16; off; off >>= 1) s += __shfl_xor_sync(~0u, s, off);
    if ((tid & 31) == 0) red[tid >> 5] = s;
    __syncthreads();
    float mean = (red[0] + red[1] + red[2] + red[3]) * (1.0f / EE);
    __syncthreads();
    float d0 = v[0] - mean, d1 = v[1] - mean, d2 = v[2] - mean;
    float sq = d0 * d0 + d1 * d1 + d2 * d2;
#pragma unroll
    for (int off = 16; off; off >>= 1) sq += __shfl_xor_sync(~0u, sq, off);
    if ((tid & 31) == 0) red[tid >> 5] = sq;
    __syncthreads();
    float var = (red[0] + red[1] + red[2] + red[3]) * (1.0f / EE);
    float inv = rsqrtf(var + 1e-5f);
#pragma unroll
    for (int i = 0; i < 3; i++) {
        int e = tid + i * 128;
        float val = (v[i] - mean) * inv * g[e] + bt[e];
        o[(size_t)row * EE + e] = val;
        if (oh) oh[(size_t)row * EE + e] = __float2half_rn(val);
    }
}

// ---------------- host orchestration ---------------------------------------
extern "C" void kernel_launch(void* const* d_in, const int* in_sizes, int n_in,
                              void* d_out, int out_size) {
    const float* enc = (const float*)d_in[0];
    const float* x   = (const float*)d_in[1];
    const float* sa1_wq = (const float*)d_in[2];
    const float* sa1_bq = (const float*)d_in[3];
    const float* sa1_wk = (const float*)d_in[4];
    const float* sa1_bk = (const float*)d_in[5];
    const float* sa1_wv = (const float*)d_in[6];
    const float* sa1_bv = (const float*)d_in[7];
    const float* sa1_pw = (const float*)d_in[8];
    const float* sa1_pb = (const float*)d_in[9];
    const float* sa2_wq = (const float*)d_in[10];
    const float* sa2_bq = (const float*)d_in[11];
    const float* sa2_wk = (const float*)d_in[12];
    const float* sa2_bk = (const float*)d_in[13];
    const float* sa2_wv = (const float*)d_in[14];
    const float* sa2_bv = (const float*)d_in[15];
    const float* sa2_pw = (const float*)d_in[16];
    const float* sa2_pb = (const float*)d_in[17];
    const float* ff_w1  = (const float*)d_in[18];
    const float* ff_b1  = (const float*)d_in[19];
    const float* ff_w2  = (const float*)d_in[20];
    const float* ff_b2  = (const float*)d_in[21];
    const float* ln1_g  = (const float*)d_in[22];
    const float* ln1_b  = (const float*)d_in[23];
    const float* ln2_g  = (const float*)d_in[24];
    const float* ln2_b  = (const float*)d_in[25];
    const float* ln3_g  = (const float*)d_in[26];
    const float* ln3_b  = (const float*)d_in[27];
    float* out = (float*)d_out;

    cudaFuncSetAttribute(gemm16_kernel,
                         cudaFuncAttributeMaxDynamicSharedMemorySize, G16_SMEM);

    __half *pqkv, *pkv, *pq, *patt, *phid, *pxh, *pench, *po1h, *po2h;
    __half *pwqkv, *pwq2, *pwkv, *pwp1, *pwp2, *pwf1, *pwf2;
    float *pbuf, *po1, *po2, *pbqkv, *pbkv, *pbq2;
    cudaGetSymbolAddress((void**)&pqkv,  g_qkv_h);
    cudaGetSymbolAddress((void**)&pkv,   g_kv_h);
    cudaGetSymbolAddress((void**)&pq,    g_q_h);
    cudaGetSymbolAddress((void**)&patt,  g_att_h);
    cudaGetSymbolAddress((void**)&phid,  g_hid_h);
    cudaGetSymbolAddress((void**)&pxh,   g_xh);
    cudaGetSymbolAddress((void**)&pench, g_ench);
    cudaGetSymbolAddress((void**)&po1h,  g_po1h);
    cudaGetSymbolAddress((void**)&po2h,  g_po2h);
    cudaGetSymbolAddress((void**)&pbuf,  g_buf);
    cudaGetSymbolAddress((void**)&po1,   g_o1);
    cudaGetSymbolAddress((void**)&po2,   g_o2);
    cudaGetSymbolAddress((void**)&pwqkv, g_wqkvh);
    cudaGetSymbolAddress((void**)&pwq2,  g_wq2h);
    cudaGetSymbolAddress((void**)&pwkv,  g_wkvh);
    cudaGetSymbolAddress((void**)&pwp1,  g_wp1h);
    cudaGetSymbolAddress((void**)&pwp2,  g_wp2h);
    cudaGetSymbolAddress((void**)&pwf1,  g_wf1h);
    cudaGetSymbolAddress((void**)&pwf2,  g_wf2h);
    cudaGetSymbolAddress((void**)&pbqkv, g_bqkv);
    cudaGetSymbolAddress((void**)&pbkv,  g_bkv);
    cudaGetSymbolAddress((void**)&pbq2,  g_bq2);

    auto gemm = [&](const __half* A, const __half* W, const float* bias,
                    float* Cf, __half* Ch, int K, int M, int relu) {
        dim3 grid(M / 128, NROWS / 128);
        gemm16_kernel<<<grid, 256, G16_SMEM>>>(A, W, bias, Cf, Ch, K, M, relu);
    };

    megapack_kernel<<<(int)((PACK_TOTAL + 255) / 256), 256>>>(
        sa1_wq, sa1_wk, sa1_wv, sa2_wq, sa2_wk, sa2_wv,
        sa1_pw, sa2_pw, ff_w1, ff_w2,
        sa1_bq, sa1_bk, sa1_bv, sa2_bq, sa2_bk, sa2_bv,
        x, enc,
        pwqkv, pwq2, pwkv, pwp1, pwp2, pwf1, pwf2,
        pbqkv, pbkv, pbq2, pxh, pench);

    // ---- block 1: masked self-attention + add&norm ----
    gemm(pxh, pwqkv, pbqkv, nullptr, pqkv, EE, 3 * EE, 0);
    attn16_kernel<<<BB * HH * 4, 128, AT_SMEM>>>(pqkv, 3 * EE,
                                                 pqkv + EE, pqkv + 2 * EE, 3 * EE, patt);
    gemm(patt, pwp1, sa1_pb, pbuf, nullptr, EE, EE, 0);
    add_ln_kernel<<<NROWS, 128>>>(x, pbuf, ln1_g, ln1_b, po1, po1h);

    // ---- block 2: cross-attention (still causal-masked) + add&norm ----
    gemm(po1h, pwq2, pbq2, nullptr, pq, EE, EE, 0);
    gemm(pench, pwkv, pbkv, nullptr, pkv, EE, 2 * EE, 0);
    attn16_kernel<<<BB * HH * 4, 128, AT_SMEM>>>(pq, EE,
                                                 pkv, pkv + EE, 2 * EE, patt);
    gemm(patt, pwp2, sa2_pb, pbuf, nullptr, EE, EE, 0);
    add_ln_kernel<<<NROWS, 128>>>(po1, pbuf, ln2_g, ln2_b, po2, po2h);

    // ---- FFN + add&norm ----
    gemm(po2h, pwf1, ff_b1, nullptr, phid, EE, FFD, 1);
    gemm(phid, pwf2, ff_b2, pbuf, nullptr, FFD, EE, 0);
    add_ln_kernel<<<NROWS, 128>>>(po2, pbuf, ln3_g, ln3_b, out, nullptr);
}

// round 7
// speedup vs baseline: 9.0318x; 1.0144x over previous
#include <cuda_runtime.h>
#include <cuda_fp16.h>
#include <cstdint>
#include <cstddef>

// Problem constants
#define EE   384
#define HH   6
#define HSS  64
#define BB   64
#define TT   256
#define FFD  1536
#define NROWS (BB*TT)          // 16384

// ---------------- scratch (device globals; no allocation allowed) ----------
__device__ __half g_qkv_h[(size_t)NROWS * 3 * EE];
__device__ __half g_kv_h[(size_t)NROWS * 2 * EE];
__device__ __half g_q_h[(size_t)NROWS * EE];
__device__ __half g_att_h[(size_t)NROWS * EE];
__device__ __half g_hid_h[(size_t)NROWS * FFD];
__device__ __half g_xh[(size_t)NROWS * EE];
__device__ __half g_ench[(size_t)NROWS * EE];
__device__ __half g_po1h[(size_t)NROWS * EE];
__device__ __half g_po2h[(size_t)NROWS * EE];
__device__ float  g_buf[(size_t)NROWS * EE];
__device__ float  g_o1[(size_t)NROWS * EE];
__device__ float  g_o2[(size_t)NROWS * EE];
// fp16 weights, transposed to [out][in]
__device__ __half g_wqkvh[3 * EE * EE];
__device__ __half g_wq2h[EE * EE];
__device__ __half g_wkvh[2 * EE * EE];
__device__ __half g_wp1h[EE * EE];
__device__ __half g_wp2h[EE * EE];
__device__ __half g_wf1h[FFD * EE];
__device__ __half g_wf2h[EE * FFD];
__device__ float  g_bqkv[3 * EE];
__device__ float  g_bkv[2 * EE];
__device__ float  g_bq2[EE];

// ---------------- PTX helpers ----------------------------------------------
__device__ __forceinline__ uint32_t smem_u32(const void* p) {
    uint32_t a;
    asm("{ .reg .u64 t; cvta.to.shared.u64 t, %1; cvt.u32.u64 %0, t; }" : "=r"(a) : "l"(p));
    return a;
}
__device__ __forceinline__ void cp16(uint32_t dst, const void* src) {
    asm volatile("cp.async.cg.shared.global [%0], [%1], 16;" :: "r"(dst), "l"(src));
}
__device__ __forceinline__ void ldsm4(uint32_t& r0, uint32_t& r1, uint32_t& r2, uint32_t& r3,
                                      uint32_t addr) {
    asm volatile("ldmatrix.sync.aligned.m8n8.x4.shared.b16 {%0,%1,%2,%3}, [%4];"
                 : "=r"(r0), "=r"(r1), "=r"(r2), "=r"(r3) : "r"(addr));
}
__device__ __forceinline__ void ldsm4t(uint32_t& r0, uint32_t& r1, uint32_t& r2, uint32_t& r3,
                                       uint32_t addr) {
    asm volatile("ldmatrix.sync.aligned.m8n8.x4.trans.shared.b16 {%0,%1,%2,%3}, [%4];"
                 : "=r"(r0), "=r"(r1), "=r"(r2), "=r"(r3) : "r"(addr));
}
__device__ __forceinline__ void mma16816(float* c, const uint32_t* a, const uint32_t* b) {
    asm volatile(
        "mma.sync.aligned.m16n8k16.row.col.f32.f16.f16.f32 "
        "{%0,%1,%2,%3}, {%4,%5,%6,%7}, {%8,%9}, {%0,%1,%2,%3};"
        : "+f"(c[0]), "+f"(c[1]), "+f"(c[2]), "+f"(c[3])
        : "r"(a[0]), "r"(a[1]), "r"(a[2]), "r"(a[3]), "r"(b[0]), "r"(b[1]));
}
__device__ __forceinline__ uint32_t ph2(float a, float b) {
    __half2 h = __floats2half2_rn(a, b);
    return *reinterpret_cast<uint32_t*>(&h);
}
// swizzled byte offset within a tile of 128B rows (64 halfs/row), seg = 16B unit
__device__ __forceinline__ uint32_t sw_off(int r, int seg) {
    return (uint32_t)(r * 128 + (((seg ^ (r & 7)) & 7) << 4));
}

// ---------------- megapack: weights -> fp16 [out][in], biases, activations -
#define HPK 147456
#define S_ATTNW (6*HPK)
#define S_PROJ  (2*HPK)
#define S_FF    (EE*FFD)
#define NACT    ((size_t)NROWS*EE)
#define NACTV   ((long long)(NACT/4))
#define PACK_TOTAL ((long long)S_ATTNW + S_PROJ + 2*S_FF + 3*EE + 2*EE + EE + 2*NACTV)

__global__ void megapack_kernel(
    const float* __restrict__ wq1, const float* __restrict__ wk1, const float* __restrict__ wv1,
    const float* __restrict__ wq2, const float* __restrict__ wk2, const float* __restrict__ wv2,
    const float* __restrict__ pw1, const float* __restrict__ pw2,
    const float* __restrict__ fw1, const float* __restrict__ fw2,
    const float* __restrict__ bq1, const float* __restrict__ bk1, const float* __restrict__ bv1,
    const float* __restrict__ bq2, const float* __restrict__ bk2, const float* __restrict__ bv2,
    const float* __restrict__ x, const float* __restrict__ enc,
    __half* __restrict__ wqkv, __half* __restrict__ wqo, __half* __restrict__ wkv,
    __half* __restrict__ wp1o, __half* __restrict__ wp2o,
    __half* __restrict__ wf1o, __half* __restrict__ wf2o,
    float* __restrict__ bqkv, float* __restrict__ bkv, float* __restrict__ bq2o,
    __half* __restrict__ xh, __half* __restrict__ ench)
{
    long long idx = (long long)blockIdx.x * 256 + threadIdx.x;
    if (idx >= PACK_TOTAL) return;
    const float scale = rsqrtf((float)EE);
    if (idx < S_ATTNW) {
        int reg = (int)(idx / HPK), i = (int)(idx % HPK);
        int h = i / (EE * HSS), e = (i / HSS) % EE, s = i % HSS;
        int out = h * HSS + s;
        float v; __half* dst; int rowoff;
        switch (reg) {
            case 0: v = wq1[i] * scale; dst = wqkv; rowoff = 0;      break;
            case 1: v = wk1[i];         dst = wqkv; rowoff = EE;     break;
            case 2: v = wv1[i];         dst = wqkv; rowoff = 2 * EE; break;
            case 3: v = wq2[i] * scale; dst = wqo;  rowoff = 0;      break;
            case 4: v = wk2[i];         dst = wkv;  rowoff = 0;      break;
            default: v = wv2[i];        dst = wkv;  rowoff = EE;     break;
        }
        dst[(size_t)(rowoff + out) * EE + e] = __float2half_rn(v);
        return;
    }
    idx -= S_ATTNW;
    if (idx < S_PROJ) {
        int reg = (int)(idx / HPK), i = (int)(idx % HPK);
        int e = i / EE, o = i % EE;
        (reg ? wp2o : wp1o)[(size_t)o * EE + e] = __float2half_rn((reg ? pw2 : pw1)[i]);
        return;
    }
    idx -= S_PROJ;
    if (idx < S_FF) {
        int e = (int)(idx / FFD), o = (int)(idx % FFD);
        wf1o[(size_t)o * EE + e] = __float2half_rn(fw1[idx]);
        return;
    }
    idx -= S_FF;
    if (idx < S_FF) {
        int e = (int)(idx / EE), o = (int)(idx % EE);
        wf2o[(size_t)o * FFD + e] = __float2half_rn(fw2[idx]);
        return;
    }
    idx -= S_FF;
    if (idx < 3 * EE) {
        int sub = (int)(idx / EE), jj = (int)(idx % EE);
        bqkv[idx] = sub == 0 ? bq1[jj] * scale : sub == 1 ? bk1[jj] : bv1[jj];
        return;
    }
    idx -= 3 * EE;
    if (idx < 2 * EE) { bkv[idx] = idx < EE ? bk2[idx] : bv2[idx - EE]; return; }
    idx -= 2 * EE;
    if (idx < EE) { bq2o[idx] = bq2[idx] * scale; return; }
    idx -= EE;
    const float* srcf; __half* dsth;
    if (idx < NACTV) { srcf = x; dsth = xh; }
    else { idx -= NACTV; srcf = enc; dsth = ench; }
    float4 v4 = ((const float4*)srcf)[idx];
    ((__half2*)dsth)[2 * idx]     = __floats2half2_rn(v4.x, v4.y);
    ((__half2*)dsth)[2 * idx + 1] = __floats2half2_rn(v4.z, v4.w);
}

// ---------------- fp16 tensor-core GEMM ------------------------------------
// C[N,M] = A[N,K] @ Wt[M,K]^T + bias (+resid) (opt relu). 128x128 tile,
// BK=64, 3-stage cp.async, K known at compile time.
#define G16_SMEM (3 * 32768)

template <int K>
__global__ void __launch_bounds__(256, 2)
gemm16_kernel(const __half* __restrict__ A, const __half* __restrict__ Wt,
              const float* __restrict__ bias, const float* __restrict__ resid,
              float* __restrict__ Cf, __half* __restrict__ Ch, int M, int relu)
{
    extern __shared__ __align__(128) char gsm[];
    uint32_t sbase = smem_u32(gsm);
    int tid = threadIdx.x, lane = tid & 31, warp = tid >> 5;
    int wm = warp >> 2, wn = warp & 3;
    int gid = lane >> 2, tg = lane & 3;
    int j = lane >> 3, rr = lane & 7;
    int col0 = blockIdx.x * 128, row0 = blockIdx.y * 128;

    float acc[4][4][4];
#pragma unroll
    for (int a = 0; a < 4; a++)
#pragma unroll
        for (int b = 0; b < 4; b++)
#pragma unroll
            for (int c = 0; c < 4; c++) acc[a][b][c] = 0.0f;

    constexpr int nch = K >> 6;
#define LOADC(stage, kt)                                                          \
    {                                                                             \
        uint32_t sA = sbase + (uint32_t)(stage) * 32768u;                         \
        uint32_t sB = sA + 16384u;                                                \
        _Pragma("unroll")                                                         \
        for (int i = 0; i < 4; i++) {                                             \
            int li = tid + i * 256; int r = li >> 3, sg = li & 7;                 \
            cp16(sA + sw_off(r, sg), A  + (size_t)(row0 + r) * K + (kt) + sg * 8);\
            cp16(sB + sw_off(r, sg), Wt + (size_t)(col0 + r) * K + (kt) + sg * 8);\
        }                                                                         \
        asm volatile("cp.async.commit_group;");                                   \
    }

    LOADC(0, 0);
    LOADC(1, 64);

#pragma unroll 2
    for (int it = 0; it < nch; it++) {
        if (it + 1 < nch) asm volatile("cp.async.wait_group 1;");
        else              asm volatile("cp.async.wait_group 0;");
        __syncthreads();
        if (it + 2 < nch) LOADC((it + 2) % 3, (it + 2) * 64);
        uint32_t sA = sbase + (uint32_t)(it % 3) * 32768u;
        uint32_t sB = sA + 16384u;
#pragma unroll
        for (int ks = 0; ks < 4; ks++) {
            uint32_t a[4][4], bfr[2][4];
#pragma unroll
            for (int mt = 0; mt < 4; mt++)
                ldsm4(a[mt][0], a[mt][1], a[mt][2], a[mt][3],
                      sA + sw_off(wm * 64 + mt * 16 + (j & 1) * 8 + rr, ks * 2 + (j >> 1)));
#pragma unroll
            for (int p = 0; p < 2; p++)
                ldsm4(bfr[p][0], bfr[p][1], bfr[p][2], bfr[p][3],
                      sB + sw_off(wn * 32 + p * 16 + (j >> 1) * 8 + rr, ks * 2 + (j & 1)));
#pragma unroll
            for (int mt = 0; mt < 4; mt++)
#pragma unroll
                for (int nt = 0; nt < 4; nt++)
                    mma16816(acc[mt][nt], a[mt], &bfr[nt >> 1][(nt & 1) * 2]);
        }
    }

#pragma unroll
    for (int mt = 0; mt < 4; mt++)
#pragma unroll
        for (int nt = 0; nt < 4; nt++) {
            int r0 = row0 + wm * 64 + mt * 16 + gid;
            int c0 = col0 + wn * 32 + nt * 8 + tg * 2;
            float b0 = bias[c0], b1 = bias[c0 + 1];
            float v0 = acc[mt][nt][0] + b0, v1 = acc[mt][nt][1] + b1;
            float v2 = acc[mt][nt][2] + b0, v3 = acc[mt][nt][3] + b1;
            if (resid) {
                float2 ra = *(const float2*)(resid + (size_t)r0 * M + c0);
                float2 rb = *(const float2*)(resid + (size_t)(r0 + 8) * M + c0);
                v0 += ra.x; v1 += ra.y; v2 += rb.x; v3 += rb.y;
            }
            if (relu) {
                v0 = fmaxf(v0, 0.f); v1 = fmaxf(v1, 0.f);
                v2 = fmaxf(v2, 0.f); v3 = fmaxf(v3, 0.f);
            }
            if (Cf) {
                *(float2*)(Cf + (size_t)r0 * M + c0)       = make_float2(v0, v1);
                *(float2*)(Cf + (size_t)(r0 + 8) * M + c0) = make_float2(v2, v3);
            }
            if (Ch) {
                *(__half2*)(Ch + (size_t)r0 * M + c0)       = __floats2half2_rn(v0, v1);
                *(__half2*)(Ch + (size_t)(r0 + 8) * M + c0) = __floats2half2_rn(v2, v3);
            }
        }
}

// ---------------- flash attention, fp16 mma, online softmax ----------------
#define AT_SMEM (8192 + 4 * 8192)     // sQ + double-buffered K,V

__global__ void __launch_bounds__(128)
attn16_kernel(const __half* __restrict__ Qg, int ldq,
              const __half* __restrict__ Kg, const __half* __restrict__ Vg, int ldkv,
              __half* __restrict__ Og)
{
    extern __shared__ __align__(128) char asmem[];
    uint32_t sbase = smem_u32(asmem);
    uint32_t sQ = sbase;
    int tid = threadIdx.x, lane = tid & 31, w = tid >> 5;
    int gid = lane >> 2, tg = lane & 3;
    int j = lane >> 3, rr = lane & 7;

    int bid = blockIdx.x;
    int tile = bid & 3, h = (bid >> 2) % HH, b = bid / (4 * HH);
    int t0 = tile * 64;
    int hoff = h * HSS;

    const __half* qrow = Qg + (size_t)(b * TT + t0) * ldq + hoff;
#pragma unroll
    for (int i = 0; i < 4; i++) {
        int li = tid + i * 128; int r = li >> 3, sg = li & 7;
        cp16(sQ + sw_off(r, sg), qrow + (size_t)r * ldq + sg * 8);
    }
#define KVLOAD(ut, bufi)                                                           \
    {                                                                              \
        uint32_t sK_ = sbase + 8192u + (uint32_t)(bufi) * 16384u;                  \
        uint32_t sV_ = sK_ + 8192u;                                                \
        const __half* kr = Kg + (size_t)(b * TT + (ut) * 64) * ldkv + hoff;        \
        const __half* vr = Vg + (size_t)(b * TT + (ut) * 64) * ldkv + hoff;        \
        _Pragma("unroll")                                                          \
        for (int i = 0; i < 4; i++) {                                              \
            int li = tid + i * 128; int r = li >> 3, sg = li & 7;                  \
            cp16(sK_ + sw_off(r, sg), kr + (size_t)r * ldkv + sg * 8);             \
            cp16(sV_ + sw_off(r, sg), vr + (size_t)r * ldkv + sg * 8);             \
        }                                                                          \
        asm volatile("cp.async.commit_group;");                                    \
    }
    KVLOAD(0, 0);
    asm volatile("cp.async.wait_group 0;");
    __syncthreads();

    uint32_t qf[4][4];
#pragma unroll
    for (int ks = 0; ks < 4; ks++)
        ldsm4(qf[ks][0], qf[ks][1], qf[ks][2], qf[ks][3],
              sQ + sw_off(w * 16 + (j & 1) * 8 + rr, ks * 2 + (j >> 1)));

    float o[8][4];
#pragma unroll
    for (int nt = 0; nt < 8; nt++)
#pragma unroll
        for (int e = 0; e < 4; e++) o[nt][e] = 0.0f;
    float m0 = -1e30f, m1 = -1e30f, l0 = 0.0f, l1 = 0.0f;

    for (int ut = 0; ut <= tile; ut++) {
        if (ut > 0) { asm volatile("cp.async.wait_group 0;"); __syncthreads(); }
        if (ut < tile) KVLOAD(ut + 1, (ut + 1) & 1);
        uint32_t sK = sbase + 8192u + (uint32_t)(ut & 1) * 16384u;
        uint32_t sV = sK + 8192u;

        float s[8][4];
#pragma unroll
        for (int nt = 0; nt < 8; nt++)
#pragma unroll
            for (int e = 0; e < 4; e++) s[nt][e] = 0.0f;
#pragma unroll
        for (int ks = 0; ks < 4; ks++) {
            uint32_t kb[4][4];
#pragma unroll
            for (int p = 0; p < 4; p++)
                ldsm4(kb[p][0], kb[p][1], kb[p][2], kb[p][3],
                      sK + sw_off(p * 16 + (j >> 1) * 8 + rr, ks * 2 + (j & 1)));
#pragma unroll
            for (int nt = 0; nt < 8; nt++)
                mma16816(s[nt], qf[ks], &kb[nt >> 1][(nt & 1) * 2]);
        }
        if (ut == tile) {
            int r0l = w * 16 + gid;
#pragma unroll
            for (int nt = 0; nt < 8; nt++) {
                int u0 = nt * 8 + tg * 2;
                if (u0     > r0l)     s[nt][0] = -1e30f;
                if (u0 + 1 > r0l)     s[nt][1] = -1e30f;
                if (u0     > r0l + 8) s[nt][2] = -1e30f;
                if (u0 + 1 > r0l + 8) s[nt][3] = -1e30f;
            }
        }
        float mx0 = -1e30f, mx1 = -1e30f;
#pragma unroll
        for (int nt = 0; nt < 8; nt++) {
            mx0 = fmaxf(mx0, fmaxf(s[nt][0], s[nt][1]));
            mx1 = fmaxf(mx1, fmaxf(s[nt][2], s[nt][3]));
        }
        mx0 = fmaxf(mx0, __shfl_xor_sync(~0u, mx0, 1));
        mx0 = fmaxf(mx0, __shfl_xor_sync(~0u, mx0, 2));
        mx1 = fmaxf(mx1, __shfl_xor_sync(~0u, mx1, 1));
        mx1 = fmaxf(mx1, __shfl_xor_sync(~0u, mx1, 2));
        float mn0 = fmaxf(m0, mx0), mn1 = fmaxf(m1, mx1);
        float f0 = __expf(m0 - mn0), f1 = __expf(m1 - mn1);
        m0 = mn0; m1 = mn1;
        float rs0 = 0.0f, rs1 = 0.0f;
#pragma unroll
        for (int nt = 0; nt < 8; nt++) {
            s[nt][0] = __expf(s[nt][0] - mn0); rs0 += s[nt][0];
            s[nt][1] = __expf(s[nt][1] - mn0); rs0 += s[nt][1];
            s[nt][2] = __expf(s[nt][2] - mn1); rs1 += s[nt][2];
            s[nt][3] = __expf(s[nt][3] - mn1); rs1 += s[nt][3];
        }
        rs0 += __shfl_xor_sync(~0u, rs0, 1); rs0 += __shfl_xor_sync(~0u, rs0, 2);
        rs1 += __shfl_xor_sync(~0u, rs1, 1); rs1 += __shfl_xor_sync(~0u, rs1, 2);
        l0 = l0 * f0 + rs0;
        l1 = l1 * f1 + rs1;
#pragma unroll
        for (int nt = 0; nt < 8; nt++) {
            o[nt][0] *= f0; o[nt][1] *= f0; o[nt][2] *= f1; o[nt][3] *= f1;
        }
        uint32_t pa[4][4];
#pragma unroll
        for (int kk = 0; kk < 4; kk++) {
            pa[kk][0] = ph2(s[2 * kk][0], s[2 * kk][1]);
            pa[kk][1] = ph2(s[2 * kk][2], s[2 * kk][3]);
            pa[kk][2] = ph2(s[2 * kk + 1][0], s[2 * kk + 1][1]);
            pa[kk][3] = ph2(s[2 * kk + 1][2], s[2 * kk + 1][3]);
        }
#pragma unroll
        for (int kk = 0; kk < 4; kk++) {
            uint32_t vb[4][4];
#pragma unroll
            for (int p = 0; p < 4; p++)
                ldsm4t(vb[p][0], vb[p][1], vb[p][2], vb[p][3],
                       sV + sw_off(kk * 16 + (j & 1) * 8 + rr, p * 2 + (j >> 1)));
#pragma unroll
            for (int nt = 0; nt < 8; nt++)
                mma16816(o[nt], pa[kk], &vb[nt >> 1][(nt & 1) * 2]);
        }
    }
    float i0 = 1.0f / l0, i1 = 1.0f / l1;
    __half* orow = Og + (size_t)(b * TT + t0) * EE + hoff;
#pragma unroll
    for (int nt = 0; nt < 8; nt++) {
        int c = nt * 8 + tg * 2;
        *(__half2*)(orow + (size_t)(w * 16 + gid) * EE + c) =
            __floats2half2_rn(o[nt][0] * i0, o[nt][1] * i0);
        *(__half2*)(orow + (size_t)(w * 16 + gid + 8) * EE + c) =
            __floats2half2_rn(o[nt][2] * i1, o[nt][3] * i1);
    }
}

// ---------------- LayerNorm (input already has residual added) -------------
__global__ void __launch_bounds__(128)
ln_kernel(const float* __restrict__ s_in,
          const float* __restrict__ g, const float* __restrict__ bt,
          float* __restrict__ o, __half* __restrict__ oh) {
    int row = blockIdx.x;
    int tid = threadIdx.x;
    float v[3];
#pragma unroll
    for (int i = 0; i < 3; i++)
        v[i] = s_in[(size_t)row * EE + tid + i * 128];
    __shared__ float red[4];
    float s = v[0] + v[1] + v[2];
#pragma unroll
    for (int off = 16; off; off >>= 1) s += __shfl_xor_sync(~0u, s, off);
    if ((tid & 31) == 0) red[tid >> 5] = s;
    __syncthreads();
    float mean = (red[0] + red[1] + red[2] + red[3]) * (1.0f / EE);
    __syncthreads();
    float d0 = v[0] - mean, d1 = v[1] - mean, d2 = v[2] - mean;
    float sq = d0 * d0 + d1 * d1 + d2 * d2;
#pragma unroll
    for (int off = 16; off; off >>= 1) sq += __shfl_xor_sync(~0u, sq, off);
    if ((tid & 31) == 0) red[tid >> 5] = sq;
    __syncthreads();
    float var = (red[0] + red[1] + red[2] + red[3]) * (1.0f / EE);
    float inv = rsqrtf(var + 1e-5f);
#pragma unroll
    for (int i = 0; i < 3; i++) {
        int e = tid + i * 128;
        float val = (v[i] - mean) * inv * g[e] + bt[e];
        o[(size_t)row * EE + e] = val;
        if (oh) oh[(size_t)row * EE + e] = __float2half_rn(val);
    }
}

// ---------------- host orchestration ---------------------------------------
extern "C" void kernel_launch(void* const* d_in, const int* in_sizes, int n_in,
                              void* d_out, int out_size) {
    const float* enc = (const float*)d_in[0];
    const float* x   = (const float*)d_in[1];
    const float* sa1_wq = (const float*)d_in[2];
    const float* sa1_bq = (const float*)d_in[3];
    const float* sa1_wk = (const float*)d_in[4];
    const float* sa1_bk = (const float*)d_in[5];
    const float* sa1_wv = (const float*)d_in[6];
    const float* sa1_bv = (const float*)d_in[7];
    const float* sa1_pw = (const float*)d_in[8];
    const float* sa1_pb = (const float*)d_in[9];
    const float* sa2_wq = (const float*)d_in[10];
    const float* sa2_bq = (const float*)d_in[11];
    const float* sa2_wk = (const float*)d_in[12];
    const float* sa2_bk = (const float*)d_in[13];
    const float* sa2_wv = (const float*)d_in[14];
    const float* sa2_bv = (const float*)d_in[15];
    const float* sa2_pw = (const float*)d_in[16];
    const float* sa2_pb = (const float*)d_in[17];
    const float* ff_w1  = (const float*)d_in[18];
    const float* ff_b1  = (const float*)d_in[19];
    const float* ff_w2  = (const float*)d_in[20];
    const float* ff_b2  = (const float*)d_in[21];
    const float* ln1_g  = (const float*)d_in[22];
    const float* ln1_b  = (const float*)d_in[23];
    const float* ln2_g  = (const float*)d_in[24];
    const float* ln2_b  = (const float*)d_in[25];
    const float* ln3_g  = (const float*)d_in[26];
    const float* ln3_b  = (const float*)d_in[27];
    float* out = (float*)d_out;

    cudaFuncSetAttribute(gemm16_kernel<384>,
                         cudaFuncAttributeMaxDynamicSharedMemorySize, G16_SMEM);
    cudaFuncSetAttribute(gemm16_kernel<1536>,
                         cudaFuncAttributeMaxDynamicSharedMemorySize, G16_SMEM);

    __half *pqkv, *pkv, *pq, *patt, *phid, *pxh, *pench, *po1h, *po2h;
    __half *pwqkv, *pwq2, *pwkv, *pwp1, *pwp2, *pwf1, *pwf2;
    float *pbuf, *po1, *po2, *pbqkv, *pbkv, *pbq2;
    cudaGetSymbolAddress((void**)&pqkv,  g_qkv_h);
    cudaGetSymbolAddress((void**)&pkv,   g_kv_h);
    cudaGetSymbolAddress((void**)&pq,    g_q_h);
    cudaGetSymbolAddress((void**)&patt,  g_att_h);
    cudaGetSymbolAddress((void**)&phid,  g_hid_h);
    cudaGetSymbolAddress((void**)&pxh,   g_xh);
    cudaGetSymbolAddress((void**)&pench, g_ench);
    cudaGetSymbolAddress((void**)&po1h,  g_po1h);
    cudaGetSymbolAddress((void**)&po2h,  g_po2h);
    cudaGetSymbolAddress((void**)&pbuf,  g_buf);
    cudaGetSymbolAddress((void**)&po1,   g_o1);
    cudaGetSymbolAddress((void**)&po2,   g_o2);
    cudaGetSymbolAddress((void**)&pwqkv, g_wqkvh);
    cudaGetSymbolAddress((void**)&pwq2,  g_wq2h);
    cudaGetSymbolAddress((void**)&pwkv,  g_wkvh);
    cudaGetSymbolAddress((void**)&pwp1,  g_wp1h);
    cudaGetSymbolAddress((void**)&pwp2,  g_wp2h);
    cudaGetSymbolAddress((void**)&pwf1,  g_wf1h);
    cudaGetSymbolAddress((void**)&pwf2,  g_wf2h);
    cudaGetSymbolAddress((void**)&pbqkv, g_bqkv);
    cudaGetSymbolAddress((void**)&pbkv,  g_bkv);
    cudaGetSymbolAddress((void**)&pbq2,  g_bq2);

    auto gemm384 = [&](const __half* A, const __half* W, const float* bias,
                       const float* resid, float* Cf, __half* Ch, int M, int relu) {
        dim3 grid(M / 128, NROWS / 128);
        gemm16_kernel<384><<<grid, 256, G16_SMEM>>>(A, W, bias, resid, Cf, Ch, M, relu);
    };

    megapack_kernel<<<(int)((PACK_TOTAL + 255) / 256), 256>>>(
        sa1_wq, sa1_wk, sa1_wv, sa2_wq, sa2_wk, sa2_wv,
        sa1_pw, sa2_pw, ff_w1, ff_w2,
        sa1_bq, sa1_bk, sa1_bv, sa2_bq, sa2_bk, sa2_bv,
        x, enc,
        pwqkv, pwq2, pwkv, pwp1, pwp2, pwf1, pwf2,
        pbqkv, pbkv, pbq2, pxh, pench);

    // ---- block 1: masked self-attention + add&norm ----
    gemm384(pxh, pwqkv, pbqkv, nullptr, nullptr, pqkv, 3 * EE, 0);
    attn16_kernel<<<BB * HH * 4, 128, AT_SMEM>>>(pqkv, 3 * EE,
                                                 pqkv + EE, pqkv + 2 * EE, 3 * EE, patt);
    gemm384(patt, pwp1, sa1_pb, x, pbuf, nullptr, EE, 0);       // pbuf = x + proj
    ln_kernel<<<NROWS, 128>>>(pbuf, ln1_g, ln1_b, po1, po1h);

    // ---- block 2: cross-attention (still causal-masked) + add&norm ----
    gemm384(po1h, pwq2, pbq2, nullptr, nullptr, pq, EE, 0);
    gemm384(pench, pwkv, pbkv, nullptr, nullptr, pkv, 2 * EE, 0);
    attn16_kernel<<<BB * HH * 4, 128, AT_SMEM>>>(pq, EE,
                                                 pkv, pkv + EE, 2 * EE, patt);
    gemm384(patt, pwp2, sa2_pb, po1, pbuf, nullptr, EE, 0);     // pbuf = o1 + proj
    ln_kernel<<<NROWS, 128>>>(pbuf, ln2_g, ln2_b, po2, po2h);

    // ---- FFN + add&norm ----
    gemm384(po2h, pwf1, ff_b1, nullptr, nullptr, phid, FFD, 1);
    {
        dim3 grid(EE / 128, NROWS / 128);
        gemm16_kernel<1536><<<grid, 256, G16_SMEM>>>(phid, pwf2, ff_b2, po2,
                                                     pbuf, nullptr, EE, 0);
    }
    ln_kernel<<<NROWS, 128>>>(pbuf, ln3_g, ln3_b, out, nullptr);
}